// round 12
// baseline (speedup 1.0000x reference)
#include <cuda_runtime.h>
#include <cuda_bf16.h>
#include <cstdint>

#define NNODE 65536
#define NEDGE 1048576
#define NLAYER 3

// ---------------- scratch (static device globals) ---------------------------
__device__ float g_dinv[NNODE];
__device__ int   g_indeg[NNODE];
__device__ int   g_rowptr[NNODE + 1];
__device__ int   g_cursor[NNODE];
__device__ int   g_csr[NEDGE];
__device__ int   g_part[256];
__device__ float g_A[3][64 * 64];              // [A, A^2, A^3] stacked
__device__ __nv_bfloat16 g_Ahi[3 * 4096], g_Alo[3 * 4096];
__device__ float g_bsum[NLAYER][128];
__device__ float g_Y[(size_t)3 * NNODE * 128]; // mixed features
__device__ float g_X[(size_t)NNODE * 128];
__device__ float g_S[(size_t)NNODE * 128];
__device__ float g_Z[(size_t)NNODE * 128];
// bf16 split weights, transposed to [n][k]
__device__ __nv_bfloat16 g_WLhi[3][128 * 512], g_WLlo[3][128 * 512];
__device__ __nv_bfloat16 g_W1hi[128 * 128],    g_W1lo[128 * 128];
__device__ __nv_bfloat16 g_W2hi[64 * 128],     g_W2lo[64 * 128];

// ================= helpers ====================================================
__device__ __forceinline__ uint32_t smem_to_u32(const void* p) {
    uint32_t a;
    asm("{ .reg .u64 t; cvta.to.shared.u64 t, %1; cvt.u32.u64 %0, t; }" : "=r"(a) : "l"(p));
    return a;
}
#define SMEM_SWIZZLE_128B(o) ((o) ^ (((o) >> 3) & 0x70))

#define LDSM_X4(r0, r1, r2, r3, addr) \
    asm volatile("ldmatrix.sync.aligned.m8n8.x4.shared.b16 {%0,%1,%2,%3}, [%4];" \
                 : "=r"(r0), "=r"(r1), "=r"(r2), "=r"(r3) : "r"(addr))

__device__ __forceinline__ void mma16816(float* c, const uint32_t* a, const uint32_t* b) {
    asm volatile(
        "mma.sync.aligned.m16n8k16.row.col.f32.bf16.bf16.f32 "
        "{%0,%1,%2,%3}, {%4,%5,%6,%7}, {%8,%9}, {%0,%1,%2,%3};"
        : "+f"(c[0]), "+f"(c[1]), "+f"(c[2]), "+f"(c[3])
        : "r"(a[0]), "r"(a[1]), "r"(a[2]), "r"(a[3]), "r"(b[0]), "r"(b[1]));
}

__device__ __forceinline__ void bf16split4(float4 v, uint2& hp, uint2& lp) {
    __nv_bfloat16 h0 = __float2bfloat16(v.x), h1 = __float2bfloat16(v.y);
    __nv_bfloat16 h2 = __float2bfloat16(v.z), h3 = __float2bfloat16(v.w);
    __nv_bfloat16 l0 = __float2bfloat16(v.x - __bfloat162float(h0));
    __nv_bfloat16 l1 = __float2bfloat16(v.y - __bfloat162float(h1));
    __nv_bfloat16 l2 = __float2bfloat16(v.z - __bfloat162float(h2));
    __nv_bfloat16 l3 = __float2bfloat16(v.w - __bfloat162float(h3));
    hp.x = (uint32_t)*(unsigned short*)&h0 | ((uint32_t)*(unsigned short*)&h1 << 16);
    hp.y = (uint32_t)*(unsigned short*)&h2 | ((uint32_t)*(unsigned short*)&h3 << 16);
    lp.x = (uint32_t)*(unsigned short*)&l0 | ((uint32_t)*(unsigned short*)&l1 << 16);
    lp.y = (uint32_t)*(unsigned short*)&l2 | ((uint32_t)*(unsigned short*)&l3 << 16);
}

// ---------------- graph preprocessing ---------------------------------------
__global__ void k_init() {
    int i = blockIdx.x * blockDim.x + threadIdx.x;
    if (i < NNODE) { g_indeg[i] = 0; g_cursor[i] = 0; }
}
__global__ void k_hist(const int* __restrict__ dst) {
    int e = blockIdx.x * blockDim.x + threadIdx.x;
    if (e < NEDGE) atomicAdd(&g_indeg[dst[e]], 1);
}
__global__ void k_scan_partial() {
    __shared__ int sh[256];
    int b = blockIdx.x, t = threadIdx.x;
    sh[t] = g_indeg[b * 256 + t];
    __syncthreads();
    for (int s = 128; s > 0; s >>= 1) {
        if (t < s) sh[t] += sh[t + s];
        __syncthreads();
    }
    if (t == 0) g_part[b] = sh[0];
}
__global__ void k_scan_block() {
    __shared__ int sh[256];
    int t = threadIdx.x;
    int v = g_part[t];
    sh[t] = v;
    __syncthreads();
    for (int off = 1; off < 256; off <<= 1) {
        int xv = (t >= off) ? sh[t - off] : 0;
        __syncthreads();
        sh[t] += xv;
        __syncthreads();
    }
    g_part[t] = sh[t] - v;
}
__global__ void k_scan_final() {
    __shared__ int sh[256];
    int b = blockIdx.x, t = threadIdx.x;
    int v = g_indeg[b * 256 + t];
    sh[t] = v;
    __syncthreads();
    for (int off = 1; off < 256; off <<= 1) {
        int xv = (t >= off) ? sh[t - off] : 0;
        __syncthreads();
        sh[t] += xv;
        __syncthreads();
    }
    int excl = sh[t] - v + g_part[b];
    g_rowptr[b * 256 + t] = excl;
    if (b == 255 && t == 255) g_rowptr[NNODE] = excl + v;
    g_dinv[b * 256 + t] = rsqrtf((float)(v + 1));
}
__global__ void k_fill(const int* __restrict__ src, const int* __restrict__ dst) {
    int e = blockIdx.x * blockDim.x + threadIdx.x;
    if (e < NEDGE) {
        int d = dst[e];
        int p = atomicAdd(&g_cursor[d], 1);
        g_csr[g_rowptr[d] + p] = src[e];
    }
}

// ---------------- fused meta prep: copy + A^2 + A^3 + bf16 split (1 block) ----
__global__ void __launch_bounds__(1024) k_metaprep(const float* __restrict__ adj) {
    float* Af = &g_A[0][0];
    int tid = threadIdx.x;
    for (int i = tid; i < 4096; i += 1024) Af[i] = adj[i];
    __syncthreads();
    {   // A^2 = A @ A
        int c = tid & 63;
        for (int r = tid >> 6; r < 64; r += 16) {
            float s = 0.f;
#pragma unroll 16
            for (int k = 0; k < 64; k++) s += Af[r * 64 + k] * Af[k * 64 + c];
            Af[4096 + r * 64 + c] = s;
        }
    }
    __syncthreads();
    {   // A^3 = A^2 @ A
        int c = tid & 63;
        for (int r = tid >> 6; r < 64; r += 16) {
            float s = 0.f;
#pragma unroll 16
            for (int k = 0; k < 64; k++) s += Af[4096 + r * 64 + k] * Af[k * 64 + c];
            Af[8192 + r * 64 + c] = s;
        }
    }
    __syncthreads();
    for (int i = tid; i < 3 * 4096; i += 1024) {
        float v = Af[i];
        __nv_bfloat16 h = __float2bfloat16(v);
        g_Ahi[i] = h;
        g_Alo[i] = __float2bfloat16(v - __bfloat162float(h));
    }
}
__global__ void k_bsum(const float* __restrict__ gb) {
    int i = blockIdx.x * blockDim.x + threadIdx.x;
    if (i < NLAYER * 128) {
        int l = i / 128, c = i % 128;
        float s = 0.f;
        for (int j = 0; j < 4; j++) s += gb[(l * 4 + j) * 128 + c];
        g_bsum[l][c] = s;
    }
}

// weight prep: W[K x N] -> Wt_hi/lo[n][k] bf16 split
__global__ void k_wprep(const float* __restrict__ W, __nv_bfloat16* __restrict__ hi,
                        __nv_bfloat16* __restrict__ lo, int K, int N) {
    int idx = blockIdx.x * 256 + threadIdx.x;
    if (idx >= K * N) return;
    int n = idx / K, k = idx % K;
    float v = W[(size_t)k * N + n];
    __nv_bfloat16 h = __float2bfloat16(v);
    hi[idx] = h;
    lo[idx] = __float2bfloat16(v - __bfloat162float(h));
}

// ---------------- HMMA mix: Y_i[64 x 131072] = A_i[64x64] @ X[64x131072] ------
// grid (2048, 3), block 256. X tile transposed through a padded fp32 smem stage
// (conflict-free both directions), then packed uint2 stores like the A-fill.
__global__ void __launch_bounds__(256) k_mixmma(const float* __restrict__ X,
                                                float* __restrict__ Y) {
    __shared__ __align__(1024) unsigned char sAh[8192];   // 64 n-rows x 64 bf16
    __shared__ __align__(1024) unsigned char sAl[8192];
    __shared__ __align__(1024) unsigned char sXh[8192];   // 64 col-rows x 64(j) bf16
    __shared__ __align__(1024) unsigned char sXl[8192];
    __shared__ float sStage[32][65];                      // transpose stage
    const uint32_t aHiA = smem_to_u32(sAh), aLoA = smem_to_u32(sAl);
    const uint32_t xHiA = smem_to_u32(sXh), xLoA = smem_to_u32(sXl);
    int tid = threadIdx.x, lane = tid & 31, wid = tid >> 5;
    int wm = wid & 3, wn = wid >> 2;
    int i = blockIdx.y;
    int col0 = blockIdx.x * 64;
    int g = lane >> 2, t4 = lane & 3;
    int aRow = lane & 15, aKb = (lane >> 4) * 16;
    int bRow = ((lane >> 4) << 3) + (lane & 7);
    int bKb  = ((lane >> 3) & 1) * 16;

    // load A_i (pre-split bf16): FULL 64x16 uint2 tile
#pragma unroll
    for (int q = 0; q < 4; q++) {
        int idx = tid + 256 * q;               // 0..1023
        int row = idx >> 4, k4 = (idx & 15) * 4;
        uint2 h = *(const uint2*)(g_Ahi + i * 4096 + row * 64 + k4);
        uint2 l = *(const uint2*)(g_Alo + i * 4096 + row * 64 + k4);
        uint32_t sw = SMEM_SWIZZLE_128B((uint32_t)(row * 128 + k4 * 2));
        *(uint2*)(sAh + sw) = h;
        *(uint2*)(sAl + sw) = l;
    }
    // X tile 64(j) x 64(col): stage 32 j-rows at a time in padded fp32,
    // then write transposed [col][j] bf16 as packed uint2 (4 j's per store).
#pragma unroll
    for (int hh = 0; hh < 2; hh++) {
#pragma unroll
        for (int q = 0; q < 2; q++) {
            int idx = tid + 256 * q;           // 0..511
            int jj = idx >> 4, c4 = (idx & 15) * 4;
            float4 v = *(const float4*)(X + (size_t)(hh * 32 + jj) * 131072 + col0 + c4);
            sStage[jj][c4 + 0] = v.x; sStage[jj][c4 + 1] = v.y;
            sStage[jj][c4 + 2] = v.z; sStage[jj][c4 + 3] = v.w;
        }
        __syncthreads();
#pragma unroll
        for (int q = 0; q < 2; q++) {
            int idx = tid + 256 * q;           // 0..511
            int col = idx & 63, j4 = idx >> 6; // j4 0..7
            float4 v = make_float4(sStage[j4 * 4 + 0][col], sStage[j4 * 4 + 1][col],
                                   sStage[j4 * 4 + 2][col], sStage[j4 * 4 + 3][col]);
            uint2 hp, lp;
            bf16split4(v, hp, lp);
            uint32_t sw = SMEM_SWIZZLE_128B((uint32_t)(col * 128 + (hh * 32 + j4 * 4) * 2));
            *(uint2*)(sXh + sw) = hp;
            *(uint2*)(sXl + sw) = lp;
        }
        __syncthreads();
    }

    float acc[4][4] = {};
#pragma unroll
    for (int ks = 0; ks < 4; ks++) {
        uint32_t ah[4], al[4];
        uint32_t aOff = SMEM_SWIZZLE_128B(
            (uint32_t)((wm * 16 + aRow) * 128 + ks * 32 + aKb));
        LDSM_X4(ah[0], ah[1], ah[2], ah[3], aHiA + aOff);
        LDSM_X4(al[0], al[1], al[2], al[3], aLoA + aOff);
        uint32_t bh[4][2], bl[4][2];
#pragma unroll
        for (int np = 0; np < 2; np++) {
            int nb = wn * 32 + np * 16;
            uint32_t bOff = SMEM_SWIZZLE_128B(
                (uint32_t)((nb + bRow) * 128 + ks * 32 + bKb));
            LDSM_X4(bh[2 * np][0], bh[2 * np][1], bh[2 * np + 1][0], bh[2 * np + 1][1],
                    xHiA + bOff);
            LDSM_X4(bl[2 * np][0], bl[2 * np][1], bl[2 * np + 1][0], bl[2 * np + 1][1],
                    xLoA + bOff);
        }
#pragma unroll
        for (int nt = 0; nt < 4; nt++) {
            mma16816(acc[nt], ah, bh[nt]);
            mma16816(acc[nt], al, bh[nt]);
            mma16816(acc[nt], ah, bl[nt]);
        }
    }

    float* Yi = Y + (size_t)i * NNODE * 128;
#pragma unroll
    for (int half = 0; half < 2; half++) {
        int r = wm * 16 + g + half * 8;        // meta-node row n
        float* Yr = Yi + (size_t)r * 131072;
#pragma unroll
        for (int nt = 0; nt < 4; nt++) {
            int col = col0 + wn * 32 + nt * 8 + t4 * 2;
            *(float2*)(Yr + col) = make_float2(acc[nt][half * 2 + 0],
                                               acc[nt][half * 2 + 1]);
        }
    }
}

// ---------------- mma.sync node GEMM (STATIC 48KB smem, 128x64 tile) ----------
// C[65536 x NOUT] = Acat[65536 x (nChunks*64)] @ Wt^T (bf16 2-term split, 3 products)
// grid = (512, NOUT/64). Warps 4x2, each m32 x n32.
// MODE 0: raw H; MODE 1: relu(+bias); MODE 2: +bias.
template <int NOUT, int MODE>
__global__ void __launch_bounds__(256) k_mma(
    const float* __restrict__ A0, const float* __restrict__ A1,
    const __nv_bfloat16* __restrict__ wtHi, const __nv_bfloat16* __restrict__ wtLo,
    const float* __restrict__ bias, float* __restrict__ C, int nChunks)
{
    __shared__ __align__(1024) unsigned char sAh[16384];  // 128 rows x 64 bf16
    __shared__ __align__(1024) unsigned char sAl[16384];
    __shared__ __align__(1024) unsigned char sBh[8192];   // 64 rows x 64 bf16
    __shared__ __align__(1024) unsigned char sBl[8192];
    const uint32_t aHiA = smem_to_u32(sAh), aLoA = smem_to_u32(sAl);
    const uint32_t bHiA = smem_to_u32(sBh), bLoA = smem_to_u32(sBl);
    int tid = threadIdx.x, lane = tid & 31, wid = tid >> 5;
    int wm = wid & 3, wn = wid >> 2;          // 4x2 warps, each m32 x n32
    int row0 = blockIdx.x * 128;
    int n0   = blockIdx.y * 64;
    int Ktot = nChunks * 64;
    int g = lane >> 2, t4 = lane & 3;
    int aRow = lane & 15;
    int aKb  = (lane >> 4) * 16;
    int bRow = ((lane >> 4) << 3) + (lane & 7);
    int bKb  = ((lane >> 3) & 1) * 16;

    float acc[2][4][4] = {};

    for (int c = 0; c < nChunks; c++) {
        const float* S;
        int kk;
        if (c < 2) { S = A0; kk = c * 64; }
        else { S = A1 + (size_t)((c - 2) >> 1) * ((size_t)NNODE * 128); kk = (c & 1) * 64; }
        const int kb = c * 64;
        const float* ap = S + (size_t)row0 * 128 + kk;
        // A tile: 128 rows x 64 fp32 -> hi/lo bf16 (2048 uint2 units)
#pragma unroll
        for (int q = 0; q < 8; q++) {
            int idx = tid + 256 * q;
            int row = idx >> 4, k4 = (idx & 15) * 4;
            float4 v = *(const float4*)(ap + (size_t)row * 128 + k4);
            uint2 hp, lp;
            bf16split4(v, hp, lp);
            uint32_t sw = SMEM_SWIZZLE_128B((uint32_t)(row * 128 + k4 * 2));
            *(uint2*)(sAh + sw) = hp;
            *(uint2*)(sAl + sw) = lp;
        }
        // B tile: 64 rows x 64 bf16 hi/lo (1024 uint2 units)
#pragma unroll
        for (int q = 0; q < 4; q++) {
            int idx = tid + 256 * q;
            int row = idx >> 4, k4 = (idx & 15) * 4;
            uint2 h = *(const uint2*)(wtHi + (size_t)(n0 + row) * Ktot + kb + k4);
            uint2 l = *(const uint2*)(wtLo + (size_t)(n0 + row) * Ktot + kb + k4);
            uint32_t sw = SMEM_SWIZZLE_128B((uint32_t)(row * 128 + k4 * 2));
            *(uint2*)(sBh + sw) = h;
            *(uint2*)(sBl + sw) = l;
        }
        __syncthreads();
#pragma unroll
        for (int ks = 0; ks < 4; ks++) {
            uint32_t ah[2][4], al[2][4];
#pragma unroll
            for (int mt = 0; mt < 2; mt++) {
                uint32_t aOff = SMEM_SWIZZLE_128B(
                    (uint32_t)((wm * 32 + mt * 16 + aRow) * 128 + ks * 32 + aKb));
                LDSM_X4(ah[mt][0], ah[mt][1], ah[mt][2], ah[mt][3], aHiA + aOff);
                LDSM_X4(al[mt][0], al[mt][1], al[mt][2], al[mt][3], aLoA + aOff);
            }
            uint32_t bh[4][2], bl[4][2];
#pragma unroll
            for (int np = 0; np < 2; np++) {
                int nb = wn * 32 + np * 16;
                uint32_t bOff = SMEM_SWIZZLE_128B(
                    (uint32_t)((nb + bRow) * 128 + ks * 32 + bKb));
                LDSM_X4(bh[2 * np][0], bh[2 * np][1], bh[2 * np + 1][0], bh[2 * np + 1][1],
                        bHiA + bOff);
                LDSM_X4(bl[2 * np][0], bl[2 * np][1], bl[2 * np + 1][0], bl[2 * np + 1][1],
                        bLoA + bOff);
            }
#pragma unroll
            for (int mt = 0; mt < 2; mt++)
#pragma unroll
                for (int nt = 0; nt < 4; nt++) {
                    mma16816(acc[mt][nt], ah[mt], bh[nt]);
                    mma16816(acc[mt][nt], al[mt], bh[nt]);
                    mma16816(acc[mt][nt], ah[mt], bl[nt]);
                }
        }
        __syncthreads();
    }

#pragma unroll
    for (int mt = 0; mt < 2; mt++) {
#pragma unroll
        for (int half = 0; half < 2; half++) {
            int r = row0 + wm * 32 + mt * 16 + g + half * 8;
            float* Cr = C + (size_t)r * NOUT;
#pragma unroll
            for (int nt = 0; nt < 4; nt++) {
                int col = n0 + wn * 32 + nt * 8 + t4 * 2;
                float v0 = acc[mt][nt][half * 2 + 0];
                float v1 = acc[mt][nt][half * 2 + 1];
                if (MODE >= 1) {
                    v0 += bias[col]; v1 += bias[col + 1];
                    if (MODE == 1) { v0 = fmaxf(v0, 0.f); v1 = fmaxf(v1, 0.f); }
                }
                *(float2*)(Cr + col) = make_float2(v0, v1);
            }
        }
    }
}

// ---------------- edge aggregation (normalization folded in) ------------------
__global__ void __launch_bounds__(256) k_agg(const float* __restrict__ H,
                                             const float* __restrict__ bsum,
                                             float* __restrict__ out) {
    int v = (blockIdx.x * 256 + threadIdx.x) >> 5;
    int lane = threadIdx.x & 31;
    if (v >= NNODE) return;
    float dv = g_dinv[v];
    float4 zv = *((const float4*)(H + (size_t)v * 128) + lane);
    float4 acc = make_float4(dv * zv.x, dv * zv.y, dv * zv.z, dv * zv.w);  // self loop
    int p = g_rowptr[v], p1 = g_rowptr[v + 1];
    for (; p + 3 < p1; p += 4) {
        int u0 = g_csr[p], u1 = g_csr[p + 1], u2 = g_csr[p + 2], u3 = g_csr[p + 3];
        float d0 = g_dinv[u0], d1 = g_dinv[u1], d2 = g_dinv[u2], d3 = g_dinv[u3];
        float4 z0 = *((const float4*)(H + (size_t)u0 * 128) + lane);
        float4 z1 = *((const float4*)(H + (size_t)u1 * 128) + lane);
        float4 z2 = *((const float4*)(H + (size_t)u2 * 128) + lane);
        float4 z3 = *((const float4*)(H + (size_t)u3 * 128) + lane);
        acc.x += d0 * z0.x + d1 * z1.x + d2 * z2.x + d3 * z3.x;
        acc.y += d0 * z0.y + d1 * z1.y + d2 * z2.y + d3 * z3.y;
        acc.z += d0 * z0.z + d1 * z1.z + d2 * z2.z + d3 * z3.z;
        acc.w += d0 * z0.w + d1 * z1.w + d2 * z2.w + d3 * z3.w;
    }
    for (; p < p1; p++) {
        int u = g_csr[p];
        float du = g_dinv[u];
        float4 z = *((const float4*)(H + (size_t)u * 128) + lane);
        acc.x += du * z.x; acc.y += du * z.y;
        acc.z += du * z.z; acc.w += du * z.w;
    }
    float4 b = *((const float4*)bsum + lane);
    float4 o;
    o.x = fmaxf(dv * acc.x + b.x, 0.f);
    o.y = fmaxf(dv * acc.y + b.y, 0.f);
    o.z = fmaxf(dv * acc.z + b.z, 0.f);
    o.w = fmaxf(dv * acc.w + b.w, 0.f);
    *((float4*)(out + (size_t)v * 128) + lane) = o;
}

// ---------------- host orchestration -----------------------------------------
extern "C" void kernel_launch(void* const* d_in, const int* in_sizes, int n_in,
                              void* d_out, int out_size) {
    const float* x    = (const float*)d_in[0];
    const int*   sub  = (const int*)d_in[1];
    const float* adj  = (const float*)d_in[2];
    const float* gcnW = (const float*)d_in[3];
    const float* gcnB = (const float*)d_in[4];
    const float* W1   = (const float*)d_in[5];
    const float* b1   = (const float*)d_in[6];
    const float* W2   = (const float*)d_in[7];
    const float* b2   = (const float*)d_in[8];
    float* out = (float*)d_out;

    void* p;
    float *pY, *pX, *pS, *pZ, *pB;
    __nv_bfloat16 *pWLh, *pWLl, *pW1h, *pW1l, *pW2h, *pW2l;
    cudaGetSymbolAddress(&p, g_Y);    pY = (float*)p;
    cudaGetSymbolAddress(&p, g_X);    pX = (float*)p;
    cudaGetSymbolAddress(&p, g_S);    pS = (float*)p;
    cudaGetSymbolAddress(&p, g_Z);    pZ = (float*)p;
    cudaGetSymbolAddress(&p, g_bsum); pB = (float*)p;
    cudaGetSymbolAddress(&p, g_WLhi); pWLh = (__nv_bfloat16*)p;
    cudaGetSymbolAddress(&p, g_WLlo); pWLl = (__nv_bfloat16*)p;
    cudaGetSymbolAddress(&p, g_W1hi); pW1h = (__nv_bfloat16*)p;
    cudaGetSymbolAddress(&p, g_W1lo); pW1l = (__nv_bfloat16*)p;
    cudaGetSymbolAddress(&p, g_W2hi); pW2h = (__nv_bfloat16*)p;
    cudaGetSymbolAddress(&p, g_W2lo); pW2l = (__nv_bfloat16*)p;

    // launches 1-3 are the deps of k_mma layer 0; k_mma lands in profiled slot 4
    k_metaprep<<<1, 1024>>>(adj);                                           // 1
    k_wprep<<<(512 * 128 + 255) / 256, 256>>>(gcnW, pWLh, pWLl, 512, 128);  // 2
    k_mixmma<<<dim3(2048, 3), 256>>>(x, pY);                                // 3
    k_mma<128, 0><<<dim3(512, 2), 256>>>(x, pY, pWLh, pWLl, nullptr, pZ, 8); // 4 <- ncu

    // graph preprocessing (needed before first k_agg)
    k_init<<<256, 256>>>();
    k_hist<<<NEDGE / 256, 256>>>(sub + NEDGE);
    k_scan_partial<<<256, 256>>>();
    k_scan_block<<<1, 256>>>();
    k_scan_final<<<256, 256>>>();
    k_fill<<<NEDGE / 256, 256>>>(sub, sub + NEDGE);
    // remaining weight prep
    k_wprep<<<(512 * 128 + 255) / 256, 256>>>(gcnW + 65536, pWLh + 65536, pWLl + 65536, 512, 128);
    k_wprep<<<(512 * 128 + 255) / 256, 256>>>(gcnW + 131072, pWLh + 131072, pWLl + 131072, 512, 128);
    k_wprep<<<(128 * 128 + 255) / 256, 256>>>(W1, pW1h, pW1l, 128, 128);
    k_wprep<<<(128 * 64 + 255) / 256, 256>>>(W2, pW2h, pW2l, 128, 64);
    k_bsum<<<2, 256>>>(gcnB);

    // layer 0 aggregation
    float* bufs[2] = { pX, pS };
    k_agg<<<NNODE / 8, 256>>>(pZ, pB, bufs[0]);
    const float* cur = bufs[0];
    // layers 1..2
    for (int l = 1; l < NLAYER; l++) {
        k_mixmma<<<dim3(2048, 3), 256>>>(cur, pY);
        k_mma<128, 0><<<dim3(512, 2), 256>>>(cur, pY, pWLh + (size_t)l * 65536,
                                             pWLl + (size_t)l * 65536, nullptr, pZ, 8);
        k_agg<<<NNODE / 8, 256>>>(pZ, pB + l * 128, bufs[l & 1]);
        cur = bufs[l & 1];
    }
    // MLP head
    k_mma<128, 1><<<dim3(512, 2), 256>>>(cur, nullptr, pW1h, pW1l, b1, pZ, 2);
    k_mma<64, 2><<<dim3(512, 1), 256>>>(pZ, nullptr, pW2h, pW2l, b2, out, 2);
}

// round 13
// speedup vs baseline: 1.1339x; 1.1339x over previous
#include <cuda_runtime.h>
#include <cuda_bf16.h>
#include <cstdint>

#define NNODE 65536
#define NEDGE 1048576
#define NLAYER 3

// ---------------- scratch (static device globals) ---------------------------
__device__ float g_dinv[NNODE];
__device__ int   g_indeg[NNODE];
__device__ int   g_rowptr[NNODE + 1];
__device__ int   g_cursor[NNODE];
__device__ int   g_csr[NEDGE];
__device__ int   g_part[256];
__device__ float g_A[3][64 * 64];              // [A, A^2, A^3] stacked
__device__ __nv_bfloat16 g_Ahi[3 * 4096], g_Alo[3 * 4096];
__device__ float g_bsum[NLAYER][128];
__device__ float g_Y[(size_t)3 * NNODE * 128]; // mixed features
__device__ float g_X[(size_t)NNODE * 128];
__device__ float g_S[(size_t)NNODE * 128];
__device__ float g_Z[(size_t)NNODE * 128];
// bf16 split weights, transposed to [n][k]
__device__ __nv_bfloat16 g_WLhi[3][128 * 512], g_WLlo[3][128 * 512];
__device__ __nv_bfloat16 g_W1hi[128 * 128],    g_W1lo[128 * 128];
__device__ __nv_bfloat16 g_W2hi[64 * 128],     g_W2lo[64 * 128];

// ================= helpers ====================================================
__device__ __forceinline__ uint32_t smem_to_u32(const void* p) {
    uint32_t a;
    asm("{ .reg .u64 t; cvta.to.shared.u64 t, %1; cvt.u32.u64 %0, t; }" : "=r"(a) : "l"(p));
    return a;
}
#define SMEM_SWIZZLE_128B(o) ((o) ^ (((o) >> 3) & 0x70))

#define LDSM_X4(r0, r1, r2, r3, addr) \
    asm volatile("ldmatrix.sync.aligned.m8n8.x4.shared.b16 {%0,%1,%2,%3}, [%4];" \
                 : "=r"(r0), "=r"(r1), "=r"(r2), "=r"(r3) : "r"(addr))

__device__ __forceinline__ void mma16816(float* c, const uint32_t* a, const uint32_t* b) {
    asm volatile(
        "mma.sync.aligned.m16n8k16.row.col.f32.bf16.bf16.f32 "
        "{%0,%1,%2,%3}, {%4,%5,%6,%7}, {%8,%9}, {%0,%1,%2,%3};"
        : "+f"(c[0]), "+f"(c[1]), "+f"(c[2]), "+f"(c[3])
        : "r"(a[0]), "r"(a[1]), "r"(a[2]), "r"(a[3]), "r"(b[0]), "r"(b[1]));
}

__device__ __forceinline__ void bf16split4(float4 v, uint2& hp, uint2& lp) {
    __nv_bfloat16 h0 = __float2bfloat16(v.x), h1 = __float2bfloat16(v.y);
    __nv_bfloat16 h2 = __float2bfloat16(v.z), h3 = __float2bfloat16(v.w);
    __nv_bfloat16 l0 = __float2bfloat16(v.x - __bfloat162float(h0));
    __nv_bfloat16 l1 = __float2bfloat16(v.y - __bfloat162float(h1));
    __nv_bfloat16 l2 = __float2bfloat16(v.z - __bfloat162float(h2));
    __nv_bfloat16 l3 = __float2bfloat16(v.w - __bfloat162float(h3));
    hp.x = (uint32_t)*(unsigned short*)&h0 | ((uint32_t)*(unsigned short*)&h1 << 16);
    hp.y = (uint32_t)*(unsigned short*)&h2 | ((uint32_t)*(unsigned short*)&h3 << 16);
    lp.x = (uint32_t)*(unsigned short*)&l0 | ((uint32_t)*(unsigned short*)&l1 << 16);
    lp.y = (uint32_t)*(unsigned short*)&l2 | ((uint32_t)*(unsigned short*)&l3 << 16);
}

// ---------------- graph preprocessing ---------------------------------------
__global__ void k_init() {
    int i = blockIdx.x * blockDim.x + threadIdx.x;
    if (i < NNODE) { g_indeg[i] = 0; g_cursor[i] = 0; }
}
__global__ void k_hist(const int* __restrict__ dst) {
    int e = blockIdx.x * blockDim.x + threadIdx.x;
    if (e < NEDGE) atomicAdd(&g_indeg[dst[e]], 1);
}
__global__ void k_scan_partial() {
    __shared__ int sh[256];
    int b = blockIdx.x, t = threadIdx.x;
    sh[t] = g_indeg[b * 256 + t];
    __syncthreads();
    for (int s = 128; s > 0; s >>= 1) {
        if (t < s) sh[t] += sh[t + s];
        __syncthreads();
    }
    if (t == 0) g_part[b] = sh[0];
}
__global__ void k_scan_block() {
    __shared__ int sh[256];
    int t = threadIdx.x;
    int v = g_part[t];
    sh[t] = v;
    __syncthreads();
    for (int off = 1; off < 256; off <<= 1) {
        int xv = (t >= off) ? sh[t - off] : 0;
        __syncthreads();
        sh[t] += xv;
        __syncthreads();
    }
    g_part[t] = sh[t] - v;
}
__global__ void k_scan_final() {
    __shared__ int sh[256];
    int b = blockIdx.x, t = threadIdx.x;
    int v = g_indeg[b * 256 + t];
    sh[t] = v;
    __syncthreads();
    for (int off = 1; off < 256; off <<= 1) {
        int xv = (t >= off) ? sh[t - off] : 0;
        __syncthreads();
        sh[t] += xv;
        __syncthreads();
    }
    int excl = sh[t] - v + g_part[b];
    g_rowptr[b * 256 + t] = excl;
    if (b == 255 && t == 255) g_rowptr[NNODE] = excl + v;
    g_dinv[b * 256 + t] = rsqrtf((float)(v + 1));
}
__global__ void k_fill(const int* __restrict__ src, const int* __restrict__ dst) {
    int e = blockIdx.x * blockDim.x + threadIdx.x;
    if (e < NEDGE) {
        int d = dst[e];
        int p = atomicAdd(&g_cursor[d], 1);
        g_csr[g_rowptr[d] + p] = src[e];
    }
}

// ---------------- fused meta prep: copy + A^2 + A^3 + bf16 split (1 block) ----
__global__ void __launch_bounds__(1024) k_metaprep(const float* __restrict__ adj) {
    float* Af = &g_A[0][0];
    int tid = threadIdx.x;
    for (int i = tid; i < 4096; i += 1024) Af[i] = adj[i];
    __syncthreads();
    {   // A^2 = A @ A
        int c = tid & 63;
        for (int r = tid >> 6; r < 64; r += 16) {
            float s = 0.f;
#pragma unroll 16
            for (int k = 0; k < 64; k++) s += Af[r * 64 + k] * Af[k * 64 + c];
            Af[4096 + r * 64 + c] = s;
        }
    }
    __syncthreads();
    {   // A^3 = A^2 @ A
        int c = tid & 63;
        for (int r = tid >> 6; r < 64; r += 16) {
            float s = 0.f;
#pragma unroll 16
            for (int k = 0; k < 64; k++) s += Af[4096 + r * 64 + k] * Af[k * 64 + c];
            Af[8192 + r * 64 + c] = s;
        }
    }
    __syncthreads();
    for (int i = tid; i < 3 * 4096; i += 1024) {
        float v = Af[i];
        __nv_bfloat16 h = __float2bfloat16(v);
        g_Ahi[i] = h;
        g_Alo[i] = __float2bfloat16(v - __bfloat162float(h));
    }
}
__global__ void k_bsum(const float* __restrict__ gb) {
    int i = blockIdx.x * blockDim.x + threadIdx.x;
    if (i < NLAYER * 128) {
        int l = i / 128, c = i % 128;
        float s = 0.f;
        for (int j = 0; j < 4; j++) s += gb[(l * 4 + j) * 128 + c];
        g_bsum[l][c] = s;
    }
}

// weight prep: W[K x N] -> Wt_hi/lo[n][k] bf16 split
__global__ void k_wprep(const float* __restrict__ W, __nv_bfloat16* __restrict__ hi,
                        __nv_bfloat16* __restrict__ lo, int K, int N) {
    int idx = blockIdx.x * 256 + threadIdx.x;
    if (idx >= K * N) return;
    int n = idx / K, k = idx % K;
    float v = W[(size_t)k * N + n];
    __nv_bfloat16 h = __float2bfloat16(v);
    hi[idx] = h;
    lo[idx] = __float2bfloat16(v - __bfloat162float(h));
}

// ---------------- HMMA mix (i-fused): Y_i = A_i @ X for i=0..2 ----------------
// grid 2048, block 256. X tile loaded/transposed/split ONCE; loop over i
// reloads only the tiny A_i tile. All fragment paths identical to R11/R12.
__global__ void __launch_bounds__(256) k_mixmma(const float* __restrict__ X,
                                                float* __restrict__ Y) {
    __shared__ __align__(1024) unsigned char sAh[8192];   // 64 n-rows x 64 bf16
    __shared__ __align__(1024) unsigned char sAl[8192];
    __shared__ __align__(1024) unsigned char sXh[8192];   // 64 col-rows x 64(j) bf16
    __shared__ __align__(1024) unsigned char sXl[8192];
    __shared__ float sStage[32][65];                      // transpose stage
    const uint32_t aHiA = smem_to_u32(sAh), aLoA = smem_to_u32(sAl);
    const uint32_t xHiA = smem_to_u32(sXh), xLoA = smem_to_u32(sXl);
    int tid = threadIdx.x, lane = tid & 31, wid = tid >> 5;
    int wm = wid & 3, wn = wid >> 2;
    int col0 = blockIdx.x * 64;
    int g = lane >> 2, t4 = lane & 3;
    int aRow = lane & 15, aKb = (lane >> 4) * 16;
    int bRow = ((lane >> 4) << 3) + (lane & 7);
    int bKb  = ((lane >> 3) & 1) * 16;

    // X tile 64(j) x 64(col): stage 32 j-rows at a time in padded fp32,
    // then write transposed [col][j] bf16 as packed uint2. Done ONCE.
#pragma unroll
    for (int hh = 0; hh < 2; hh++) {
#pragma unroll
        for (int q = 0; q < 2; q++) {
            int idx = tid + 256 * q;           // 0..511
            int jj = idx >> 4, c4 = (idx & 15) * 4;
            float4 v = *(const float4*)(X + (size_t)(hh * 32 + jj) * 131072 + col0 + c4);
            sStage[jj][c4 + 0] = v.x; sStage[jj][c4 + 1] = v.y;
            sStage[jj][c4 + 2] = v.z; sStage[jj][c4 + 3] = v.w;
        }
        __syncthreads();
#pragma unroll
        for (int q = 0; q < 2; q++) {
            int idx = tid + 256 * q;           // 0..511
            int col = idx & 63, j4 = idx >> 6; // j4 0..7
            float4 v = make_float4(sStage[j4 * 4 + 0][col], sStage[j4 * 4 + 1][col],
                                   sStage[j4 * 4 + 2][col], sStage[j4 * 4 + 3][col]);
            uint2 hp, lp;
            bf16split4(v, hp, lp);
            uint32_t sw = SMEM_SWIZZLE_128B((uint32_t)(col * 128 + (hh * 32 + j4 * 4) * 2));
            *(uint2*)(sXh + sw) = hp;
            *(uint2*)(sXl + sw) = lp;
        }
        __syncthreads();
    }

    for (int i = 0; i < 3; i++) {
        // protect sAh/sAl from still-in-flight LDSM of previous i
        __syncthreads();
        // load A_i (pre-split bf16): FULL 64x16 uint2 tile
#pragma unroll
        for (int q = 0; q < 4; q++) {
            int idx = tid + 256 * q;           // 0..1023
            int row = idx >> 4, k4 = (idx & 15) * 4;
            uint2 h = *(const uint2*)(g_Ahi + i * 4096 + row * 64 + k4);
            uint2 l = *(const uint2*)(g_Alo + i * 4096 + row * 64 + k4);
            uint32_t sw = SMEM_SWIZZLE_128B((uint32_t)(row * 128 + k4 * 2));
            *(uint2*)(sAh + sw) = h;
            *(uint2*)(sAl + sw) = l;
        }
        __syncthreads();

        float acc[4][4] = {};
#pragma unroll
        for (int ks = 0; ks < 4; ks++) {
            uint32_t ah[4], al[4];
            uint32_t aOff = SMEM_SWIZZLE_128B(
                (uint32_t)((wm * 16 + aRow) * 128 + ks * 32 + aKb));
            LDSM_X4(ah[0], ah[1], ah[2], ah[3], aHiA + aOff);
            LDSM_X4(al[0], al[1], al[2], al[3], aLoA + aOff);
            uint32_t bh[4][2], bl[4][2];
#pragma unroll
            for (int np = 0; np < 2; np++) {
                int nb = wn * 32 + np * 16;
                uint32_t bOff = SMEM_SWIZZLE_128B(
                    (uint32_t)((nb + bRow) * 128 + ks * 32 + bKb));
                LDSM_X4(bh[2 * np][0], bh[2 * np][1], bh[2 * np + 1][0], bh[2 * np + 1][1],
                        xHiA + bOff);
                LDSM_X4(bl[2 * np][0], bl[2 * np][1], bl[2 * np + 1][0], bl[2 * np + 1][1],
                        xLoA + bOff);
            }
#pragma unroll
            for (int nt = 0; nt < 4; nt++) {
                mma16816(acc[nt], ah, bh[nt]);
                mma16816(acc[nt], al, bh[nt]);
                mma16816(acc[nt], ah, bl[nt]);
            }
        }

        float* Yi = Y + (size_t)i * NNODE * 128;
#pragma unroll
        for (int half = 0; half < 2; half++) {
            int r = wm * 16 + g + half * 8;    // meta-node row n
            float* Yr = Yi + (size_t)r * 131072;
#pragma unroll
            for (int nt = 0; nt < 4; nt++) {
                int col = col0 + wn * 32 + nt * 8 + t4 * 2;
                *(float2*)(Yr + col) = make_float2(acc[nt][half * 2 + 0],
                                                   acc[nt][half * 2 + 1]);
            }
        }
    }
}

// ---------------- mma.sync node GEMM (R11 config: STATIC smem, 64x64 tile) ----
// C[65536 x NOUT] = Acat[65536 x (nChunks*64)] @ Wt^T (bf16 2-term split, 3 products)
// grid = (1024, NOUT/64). MODE 0: raw H; MODE 1: relu(+bias); MODE 2: +bias.
template <int NOUT, int MODE>
__global__ void __launch_bounds__(256) k_mma(
    const float* __restrict__ A0, const float* __restrict__ A1,
    const __nv_bfloat16* __restrict__ wtHi, const __nv_bfloat16* __restrict__ wtLo,
    const float* __restrict__ bias, float* __restrict__ C, int nChunks)
{
    __shared__ __align__(1024) unsigned char sAh[8192];
    __shared__ __align__(1024) unsigned char sAl[8192];
    __shared__ __align__(1024) unsigned char sBh[8192];
    __shared__ __align__(1024) unsigned char sBl[8192];
    const uint32_t aHiA = smem_to_u32(sAh), aLoA = smem_to_u32(sAl);
    const uint32_t bHiA = smem_to_u32(sBh), bLoA = smem_to_u32(sBl);
    int tid = threadIdx.x, lane = tid & 31, wid = tid >> 5;
    int wm = wid & 3, wn = wid >> 2;
    int row0 = blockIdx.x * 64;
    int n0   = blockIdx.y * 64;
    int Ktot = nChunks * 64;
    int g = lane >> 2, t4 = lane & 3;
    int aRow = lane & 15;
    int aKb  = (lane >> 4) * 16;
    int bRow = ((lane >> 4) << 3) + (lane & 7);
    int bKb  = ((lane >> 3) & 1) * 16;

    float acc[4][4] = {};

    for (int c = 0; c < nChunks; c++) {
        const float* S;
        int kk;
        if (c < 2) { S = A0; kk = c * 64; }
        else { S = A1 + (size_t)((c - 2) >> 1) * ((size_t)NNODE * 128); kk = (c & 1) * 64; }
        const int kb = c * 64;
        const float* ap = S + (size_t)row0 * 128 + kk;
#pragma unroll
        for (int q = 0; q < 4; q++) {
            int idx = tid + 256 * q;
            int row = idx >> 4, k4 = (idx & 15) * 4;
            float4 v = *(const float4*)(ap + (size_t)row * 128 + k4);
            uint2 hp, lp;
            bf16split4(v, hp, lp);
            uint32_t sw = SMEM_SWIZZLE_128B((uint32_t)(row * 128 + k4 * 2));
            *(uint2*)(sAh + sw) = hp;
            *(uint2*)(sAl + sw) = lp;
        }
#pragma unroll
        for (int q = 0; q < 4; q++) {
            int idx = tid + 256 * q;
            int row = idx >> 4, k4 = (idx & 15) * 4;
            uint2 h = *(const uint2*)(wtHi + (size_t)(n0 + row) * Ktot + kb + k4);
            uint2 l = *(const uint2*)(wtLo + (size_t)(n0 + row) * Ktot + kb + k4);
            uint32_t sw = SMEM_SWIZZLE_128B((uint32_t)(row * 128 + k4 * 2));
            *(uint2*)(sBh + sw) = h;
            *(uint2*)(sBl + sw) = l;
        }
        __syncthreads();
#pragma unroll
        for (int ks = 0; ks < 4; ks++) {
            uint32_t ah[4], al[4];
            uint32_t aOff = SMEM_SWIZZLE_128B(
                (uint32_t)((wm * 16 + aRow) * 128 + ks * 32 + aKb));
            LDSM_X4(ah[0], ah[1], ah[2], ah[3], aHiA + aOff);
            LDSM_X4(al[0], al[1], al[2], al[3], aLoA + aOff);
            uint32_t bh[4][2], bl[4][2];
#pragma unroll
            for (int np = 0; np < 2; np++) {
                int nb = wn * 32 + np * 16;
                uint32_t bOff = SMEM_SWIZZLE_128B(
                    (uint32_t)((nb + bRow) * 128 + ks * 32 + bKb));
                LDSM_X4(bh[2 * np][0], bh[2 * np][1], bh[2 * np + 1][0], bh[2 * np + 1][1],
                        bHiA + bOff);
                LDSM_X4(bl[2 * np][0], bl[2 * np][1], bl[2 * np + 1][0], bl[2 * np + 1][1],
                        bLoA + bOff);
            }
#pragma unroll
            for (int nt = 0; nt < 4; nt++) {
                mma16816(acc[nt], ah, bh[nt]);
                mma16816(acc[nt], al, bh[nt]);
                mma16816(acc[nt], ah, bl[nt]);
            }
        }
        __syncthreads();
    }

#pragma unroll
    for (int half = 0; half < 2; half++) {
        int r = row0 + wm * 16 + g + half * 8;
        float* Cr = C + (size_t)r * NOUT;
#pragma unroll
        for (int nt = 0; nt < 4; nt++) {
            int col = n0 + wn * 32 + nt * 8 + t4 * 2;
            float v0 = acc[nt][half * 2 + 0];
            float v1 = acc[nt][half * 2 + 1];
            if (MODE >= 1) {
                v0 += bias[col]; v1 += bias[col + 1];
                if (MODE == 1) { v0 = fmaxf(v0, 0.f); v1 = fmaxf(v1, 0.f); }
            }
            *(float2*)(Cr + col) = make_float2(v0, v1);
        }
    }
}

// ---------------- edge aggregation (normalization folded in) ------------------
__global__ void __launch_bounds__(256) k_agg(const float* __restrict__ H,
                                             const float* __restrict__ bsum,
                                             float* __restrict__ out) {
    int v = (blockIdx.x * 256 + threadIdx.x) >> 5;
    int lane = threadIdx.x & 31;
    if (v >= NNODE) return;
    float dv = g_dinv[v];
    float4 zv = *((const float4*)(H + (size_t)v * 128) + lane);
    float4 acc = make_float4(dv * zv.x, dv * zv.y, dv * zv.z, dv * zv.w);  // self loop
    int p = g_rowptr[v], p1 = g_rowptr[v + 1];
    for (; p + 3 < p1; p += 4) {
        int u0 = g_csr[p], u1 = g_csr[p + 1], u2 = g_csr[p + 2], u3 = g_csr[p + 3];
        float d0 = g_dinv[u0], d1 = g_dinv[u1], d2 = g_dinv[u2], d3 = g_dinv[u3];
        float4 z0 = *((const float4*)(H + (size_t)u0 * 128) + lane);
        float4 z1 = *((const float4*)(H + (size_t)u1 * 128) + lane);
        float4 z2 = *((const float4*)(H + (size_t)u2 * 128) + lane);
        float4 z3 = *((const float4*)(H + (size_t)u3 * 128) + lane);
        acc.x += d0 * z0.x + d1 * z1.x + d2 * z2.x + d3 * z3.x;
        acc.y += d0 * z0.y + d1 * z1.y + d2 * z2.y + d3 * z3.y;
        acc.z += d0 * z0.z + d1 * z1.z + d2 * z2.z + d3 * z3.z;
        acc.w += d0 * z0.w + d1 * z1.w + d2 * z2.w + d3 * z3.w;
    }
    for (; p < p1; p++) {
        int u = g_csr[p];
        float du = g_dinv[u];
        float4 z = *((const float4*)(H + (size_t)u * 128) + lane);
        acc.x += du * z.x; acc.y += du * z.y;
        acc.z += du * z.z; acc.w += du * z.w;
    }
    float4 b = *((const float4*)bsum + lane);
    float4 o;
    o.x = fmaxf(dv * acc.x + b.x, 0.f);
    o.y = fmaxf(dv * acc.y + b.y, 0.f);
    o.z = fmaxf(dv * acc.z + b.z, 0.f);
    o.w = fmaxf(dv * acc.w + b.w, 0.f);
    *((float4*)(out + (size_t)v * 128) + lane) = o;
}

// ---------------- host orchestration -----------------------------------------
extern "C" void kernel_launch(void* const* d_in, const int* in_sizes, int n_in,
                              void* d_out, int out_size) {
    const float* x    = (const float*)d_in[0];
    const int*   sub  = (const int*)d_in[1];
    const float* adj  = (const float*)d_in[2];
    const float* gcnW = (const float*)d_in[3];
    const float* gcnB = (const float*)d_in[4];
    const float* W1   = (const float*)d_in[5];
    const float* b1   = (const float*)d_in[6];
    const float* W2   = (const float*)d_in[7];
    const float* b2   = (const float*)d_in[8];
    float* out = (float*)d_out;

    void* p;
    float *pY, *pX, *pS, *pZ, *pB;
    __nv_bfloat16 *pWLh, *pWLl, *pW1h, *pW1l, *pW2h, *pW2l;
    cudaGetSymbolAddress(&p, g_Y);    pY = (float*)p;
    cudaGetSymbolAddress(&p, g_X);    pX = (float*)p;
    cudaGetSymbolAddress(&p, g_S);    pS = (float*)p;
    cudaGetSymbolAddress(&p, g_Z);    pZ = (float*)p;
    cudaGetSymbolAddress(&p, g_bsum); pB = (float*)p;
    cudaGetSymbolAddress(&p, g_WLhi); pWLh = (__nv_bfloat16*)p;
    cudaGetSymbolAddress(&p, g_WLlo); pWLl = (__nv_bfloat16*)p;
    cudaGetSymbolAddress(&p, g_W1hi); pW1h = (__nv_bfloat16*)p;
    cudaGetSymbolAddress(&p, g_W1lo); pW1l = (__nv_bfloat16*)p;
    cudaGetSymbolAddress(&p, g_W2hi); pW2h = (__nv_bfloat16*)p;
    cudaGetSymbolAddress(&p, g_W2lo); pW2l = (__nv_bfloat16*)p;

    // launches 1-3 are the deps of k_mma layer 0; k_mma lands in profiled slot 4
    k_metaprep<<<1, 1024>>>(adj);                                           // 1
    k_wprep<<<(512 * 128 + 255) / 256, 256>>>(gcnW, pWLh, pWLl, 512, 128);  // 2
    k_mixmma<<<2048, 256>>>(x, pY);                                         // 3
    k_mma<128, 0><<<dim3(1024, 2), 256>>>(x, pY, pWLh, pWLl, nullptr, pZ, 8); // 4 <- ncu

    // graph preprocessing (needed before first k_agg)
    k_init<<<256, 256>>>();
    k_hist<<<NEDGE / 256, 256>>>(sub + NEDGE);
    k_scan_partial<<<256, 256>>>();
    k_scan_block<<<1, 256>>>();
    k_scan_final<<<256, 256>>>();
    k_fill<<<NEDGE / 256, 256>>>(sub, sub + NEDGE);
    // remaining weight prep
    k_wprep<<<(512 * 128 + 255) / 256, 256>>>(gcnW + 65536, pWLh + 65536, pWLl + 65536, 512, 128);
    k_wprep<<<(512 * 128 + 255) / 256, 256>>>(gcnW + 131072, pWLh + 131072, pWLl + 131072, 512, 128);
    k_wprep<<<(128 * 128 + 255) / 256, 256>>>(W1, pW1h, pW1l, 128, 128);
    k_wprep<<<(128 * 64 + 255) / 256, 256>>>(W2, pW2h, pW2l, 128, 64);
    k_bsum<<<2, 256>>>(gcnB);

    // layer 0 aggregation
    float* bufs[2] = { pX, pS };
    k_agg<<<NNODE / 8, 256>>>(pZ, pB, bufs[0]);
    const float* cur = bufs[0];
    // layers 1..2
    for (int l = 1; l < NLAYER; l++) {
        k_mixmma<<<2048, 256>>>(cur, pY);
        k_mma<128, 0><<<dim3(1024, 2), 256>>>(cur, pY, pWLh + (size_t)l * 65536,
                                              pWLl + (size_t)l * 65536, nullptr, pZ, 8);
        k_agg<<<NNODE / 8, 256>>>(pZ, pB + l * 128, bufs[l & 1]);
        cur = bufs[l & 1];
    }
    // MLP head
    k_mma<128, 1><<<dim3(1024, 2), 256>>>(cur, nullptr, pW1h, pW1l, b1, pZ, 2);
    k_mma<64, 2><<<dim3(1024, 1), 256>>>(pZ, nullptr, pW2h, pW2l, b2, out, 2);
}

// round 14
// speedup vs baseline: 1.2891x; 1.1368x over previous
#include <cuda_runtime.h>
#include <cuda_bf16.h>
#include <cstdint>

#define NNODE 65536
#define NEDGE 1048576
#define NLAYER 3

// ---------------- scratch (static device globals) ---------------------------
__device__ float g_dinv[NNODE];
__device__ int   g_indeg[NNODE];
__device__ int   g_rowptr[NNODE + 1];
__device__ int   g_cursor[NNODE];
__device__ int   g_csr[NEDGE];
__device__ int   g_part[256];
__device__ float g_A[3][64 * 64];
__device__ __nv_bfloat16 g_Ahi[3 * 4096], g_Alo[3 * 4096];
__device__ float g_bsum[NLAYER][128];
__device__ float g_Z[(size_t)NNODE * 128];                       // raw H (fp32 for agg)
__device__ __nv_bfloat16 g_Yhi[(size_t)3 * NNODE * 128];         // mixed feats, bf16 split
__device__ __nv_bfloat16 g_Ylo[(size_t)3 * NNODE * 128];
__device__ __nv_bfloat16 g_Xhi[(size_t)NNODE * 128];             // layer input, bf16 split
__device__ __nv_bfloat16 g_Xlo[(size_t)NNODE * 128];
// bf16 split weights, transposed to [n][k]
__device__ __nv_bfloat16 g_WLhi[3][128 * 512], g_WLlo[3][128 * 512];
__device__ __nv_bfloat16 g_W1hi[128 * 128],    g_W1lo[128 * 128];
__device__ __nv_bfloat16 g_W2hi[64 * 128],     g_W2lo[64 * 128];

// ================= helpers ====================================================
__device__ __forceinline__ uint32_t smem_to_u32(const void* p) {
    uint32_t a;
    asm("{ .reg .u64 t; cvta.to.shared.u64 t, %1; cvt.u32.u64 %0, t; }" : "=r"(a) : "l"(p));
    return a;
}
#define SMEM_SWIZZLE_128B(o) ((o) ^ (((o) >> 3) & 0x70))

#define LDSM_X4(r0, r1, r2, r3, addr) \
    asm volatile("ldmatrix.sync.aligned.m8n8.x4.shared.b16 {%0,%1,%2,%3}, [%4];" \
                 : "=r"(r0), "=r"(r1), "=r"(r2), "=r"(r3) : "r"(addr))

#define CP16(dst, src) \
    asm volatile("cp.async.cg.shared.global [%0], [%1], 16;" :: "r"(dst), "l"(src))
#define CP_COMMIT() asm volatile("cp.async.commit_group;" ::: "memory")
#define CP_WAIT1()  asm volatile("cp.async.wait_group 1;" ::: "memory")
#define CP_WAIT0()  asm volatile("cp.async.wait_group 0;" ::: "memory")

__device__ __forceinline__ void mma16816(float* c, const uint32_t* a, const uint32_t* b) {
    asm volatile(
        "mma.sync.aligned.m16n8k16.row.col.f32.bf16.bf16.f32 "
        "{%0,%1,%2,%3}, {%4,%5,%6,%7}, {%8,%9}, {%0,%1,%2,%3};"
        : "+f"(c[0]), "+f"(c[1]), "+f"(c[2]), "+f"(c[3])
        : "r"(a[0]), "r"(a[1]), "r"(a[2]), "r"(a[3]), "r"(b[0]), "r"(b[1]));
}

__device__ __forceinline__ void bf16split4(float4 v, uint2& hp, uint2& lp) {
    __nv_bfloat16 h0 = __float2bfloat16(v.x), h1 = __float2bfloat16(v.y);
    __nv_bfloat16 h2 = __float2bfloat16(v.z), h3 = __float2bfloat16(v.w);
    __nv_bfloat16 l0 = __float2bfloat16(v.x - __bfloat162float(h0));
    __nv_bfloat16 l1 = __float2bfloat16(v.y - __bfloat162float(h1));
    __nv_bfloat16 l2 = __float2bfloat16(v.z - __bfloat162float(h2));
    __nv_bfloat16 l3 = __float2bfloat16(v.w - __bfloat162float(h3));
    hp.x = (uint32_t)*(unsigned short*)&h0 | ((uint32_t)*(unsigned short*)&h1 << 16);
    hp.y = (uint32_t)*(unsigned short*)&h2 | ((uint32_t)*(unsigned short*)&h3 << 16);
    lp.x = (uint32_t)*(unsigned short*)&l0 | ((uint32_t)*(unsigned short*)&l1 << 16);
    lp.y = (uint32_t)*(unsigned short*)&l2 | ((uint32_t)*(unsigned short*)&l3 << 16);
}
__device__ __forceinline__ void bf16split2(float v0, float v1, uint32_t& hp, uint32_t& lp) {
    __nv_bfloat16 h0 = __float2bfloat16(v0), h1 = __float2bfloat16(v1);
    __nv_bfloat16 l0 = __float2bfloat16(v0 - __bfloat162float(h0));
    __nv_bfloat16 l1 = __float2bfloat16(v1 - __bfloat162float(h1));
    hp = (uint32_t)*(unsigned short*)&h0 | ((uint32_t)*(unsigned short*)&h1 << 16);
    lp = (uint32_t)*(unsigned short*)&l0 | ((uint32_t)*(unsigned short*)&l1 << 16);
}

// ---------------- graph preprocessing ---------------------------------------
__global__ void k_init() {
    int i = blockIdx.x * blockDim.x + threadIdx.x;
    if (i < NNODE) { g_indeg[i] = 0; g_cursor[i] = 0; }
}
__global__ void k_hist(const int* __restrict__ dst) {
    int e = blockIdx.x * blockDim.x + threadIdx.x;
    if (e < NEDGE) atomicAdd(&g_indeg[dst[e]], 1);
}
__global__ void k_scan_partial() {
    __shared__ int sh[256];
    int b = blockIdx.x, t = threadIdx.x;
    sh[t] = g_indeg[b * 256 + t];
    __syncthreads();
    for (int s = 128; s > 0; s >>= 1) {
        if (t < s) sh[t] += sh[t + s];
        __syncthreads();
    }
    if (t == 0) g_part[b] = sh[0];
}
__global__ void k_scan_block() {
    __shared__ int sh[256];
    int t = threadIdx.x;
    int v = g_part[t];
    sh[t] = v;
    __syncthreads();
    for (int off = 1; off < 256; off <<= 1) {
        int xv = (t >= off) ? sh[t - off] : 0;
        __syncthreads();
        sh[t] += xv;
        __syncthreads();
    }
    g_part[t] = sh[t] - v;
}
__global__ void k_scan_final() {
    __shared__ int sh[256];
    int b = blockIdx.x, t = threadIdx.x;
    int v = g_indeg[b * 256 + t];
    sh[t] = v;
    __syncthreads();
    for (int off = 1; off < 256; off <<= 1) {
        int xv = (t >= off) ? sh[t - off] : 0;
        __syncthreads();
        sh[t] += xv;
        __syncthreads();
    }
    int excl = sh[t] - v + g_part[b];
    g_rowptr[b * 256 + t] = excl;
    if (b == 255 && t == 255) g_rowptr[NNODE] = excl + v;
    g_dinv[b * 256 + t] = rsqrtf((float)(v + 1));
}
__global__ void k_fill(const int* __restrict__ src, const int* __restrict__ dst) {
    int e = blockIdx.x * blockDim.x + threadIdx.x;
    if (e < NEDGE) {
        int d = dst[e];
        int p = atomicAdd(&g_cursor[d], 1);
        g_csr[g_rowptr[d] + p] = src[e];
    }
}

// ---------------- fused meta prep --------------------------------------------
__global__ void __launch_bounds__(1024) k_metaprep(const float* __restrict__ adj) {
    float* Af = &g_A[0][0];
    int tid = threadIdx.x;
    for (int i = tid; i < 4096; i += 1024) Af[i] = adj[i];
    __syncthreads();
    {
        int c = tid & 63;
        for (int r = tid >> 6; r < 64; r += 16) {
            float s = 0.f;
#pragma unroll 16
            for (int k = 0; k < 64; k++) s += Af[r * 64 + k] * Af[k * 64 + c];
            Af[4096 + r * 64 + c] = s;
        }
    }
    __syncthreads();
    {
        int c = tid & 63;
        for (int r = tid >> 6; r < 64; r += 16) {
            float s = 0.f;
#pragma unroll 16
            for (int k = 0; k < 64; k++) s += Af[4096 + r * 64 + k] * Af[k * 64 + c];
            Af[8192 + r * 64 + c] = s;
        }
    }
    __syncthreads();
    for (int i = tid; i < 3 * 4096; i += 1024) {
        float v = Af[i];
        __nv_bfloat16 h = __float2bfloat16(v);
        g_Ahi[i] = h;
        g_Alo[i] = __float2bfloat16(v - __bfloat162float(h));
    }
}
__global__ void k_bsum(const float* __restrict__ gb) {
    int i = blockIdx.x * blockDim.x + threadIdx.x;
    if (i < NLAYER * 128) {
        int l = i / 128, c = i % 128;
        float s = 0.f;
        for (int j = 0; j < 4; j++) s += gb[(l * 4 + j) * 128 + c];
        g_bsum[l][c] = s;
    }
}

// weight prep: W[K x N] -> Wt_hi/lo[n][k]
__global__ void k_wprep(const float* __restrict__ W, __nv_bfloat16* __restrict__ hi,
                        __nv_bfloat16* __restrict__ lo, int K, int N) {
    int idx = blockIdx.x * 256 + threadIdx.x;
    if (idx >= K * N) return;
    int n = idx / K, k = idx % K;
    float v = W[(size_t)k * N + n];
    __nv_bfloat16 h = __float2bfloat16(v);
    hi[idx] = h;
    lo[idx] = __float2bfloat16(v - __bfloat162float(h));
}

// x fp32 -> Xhi/Xlo bf16 split (one-time, layer 0)
__global__ void k_xprep(const float* __restrict__ x) {
    int idx = blockIdx.x * 256 + threadIdx.x;          // 2M float4 units
    float4 v = *((const float4*)x + idx);
    uint2 hp, lp;
    bf16split4(v, hp, lp);
    *((uint2*)g_Xhi + idx) = hp;
    *((uint2*)g_Xlo + idx) = lp;
}

// ---------------- HMMA mix (i-fused, bf16-pair I/O) ---------------------------
// Y_i = A_i @ X, i=0..2; X read from Xhi/Xlo, Y written as Yhi/Ylo.
__global__ void __launch_bounds__(256) k_mixmma(const __nv_bfloat16* __restrict__ Xh,
                                                const __nv_bfloat16* __restrict__ Xl,
                                                __nv_bfloat16* __restrict__ Yh,
                                                __nv_bfloat16* __restrict__ Yl) {
    __shared__ __align__(1024) unsigned char sAh[8192];
    __shared__ __align__(1024) unsigned char sAl[8192];
    __shared__ __align__(1024) unsigned char sXh[8192];   // transposed [col][j]
    __shared__ __align__(1024) unsigned char sXl[8192];
    __shared__ unsigned short sStH[32][68];
    __shared__ unsigned short sStL[32][68];
    const uint32_t aHiA = smem_to_u32(sAh), aLoA = smem_to_u32(sAl);
    const uint32_t xHiA = smem_to_u32(sXh), xLoA = smem_to_u32(sXl);
    int tid = threadIdx.x, lane = tid & 31, wid = tid >> 5;
    int wm = wid & 3, wn = wid >> 2;
    int col0 = blockIdx.x * 64;
    int g = lane >> 2, t4 = lane & 3;
    int aRow = lane & 15, aKb = (lane >> 4) * 16;
    int bRow = ((lane >> 4) << 3) + (lane & 7);
    int bKb  = ((lane >> 3) & 1) * 16;

    // X tile 64(j) x 64(col) bf16 pair: stage 32 rows, transpose, store swizzled
#pragma unroll
    for (int hh = 0; hh < 2; hh++) {
#pragma unroll
        for (int q = 0; q < 2; q++) {
            int idx = tid + 256 * q;           // 0..511
            int jj = idx >> 4, c4 = (idx & 15) * 4;
            size_t gofs = (size_t)(hh * 32 + jj) * 131072 + col0 + c4;
            *(uint2*)&sStH[jj][c4] = *(const uint2*)(Xh + gofs);
            *(uint2*)&sStL[jj][c4] = *(const uint2*)(Xl + gofs);
        }
        __syncthreads();
#pragma unroll
        for (int q = 0; q < 2; q++) {
            int idx = tid + 256 * q;
            int col = idx & 63, j4 = idx >> 6;
            uint2 hp, lp;
            hp.x = (uint32_t)sStH[j4 * 4 + 0][col] | ((uint32_t)sStH[j4 * 4 + 1][col] << 16);
            hp.y = (uint32_t)sStH[j4 * 4 + 2][col] | ((uint32_t)sStH[j4 * 4 + 3][col] << 16);
            lp.x = (uint32_t)sStL[j4 * 4 + 0][col] | ((uint32_t)sStL[j4 * 4 + 1][col] << 16);
            lp.y = (uint32_t)sStL[j4 * 4 + 2][col] | ((uint32_t)sStL[j4 * 4 + 3][col] << 16);
            uint32_t sw = SMEM_SWIZZLE_128B((uint32_t)(col * 128 + (hh * 32 + j4 * 4) * 2));
            *(uint2*)(sXh + sw) = hp;
            *(uint2*)(sXl + sw) = lp;
        }
        __syncthreads();
    }

    for (int i = 0; i < 3; i++) {
        __syncthreads();
#pragma unroll
        for (int q = 0; q < 4; q++) {
            int idx = tid + 256 * q;
            int row = idx >> 4, k4 = (idx & 15) * 4;
            uint2 h = *(const uint2*)(g_Ahi + i * 4096 + row * 64 + k4);
            uint2 l = *(const uint2*)(g_Alo + i * 4096 + row * 64 + k4);
            uint32_t sw = SMEM_SWIZZLE_128B((uint32_t)(row * 128 + k4 * 2));
            *(uint2*)(sAh + sw) = h;
            *(uint2*)(sAl + sw) = l;
        }
        __syncthreads();

        float acc[4][4] = {};
#pragma unroll
        for (int ks = 0; ks < 4; ks++) {
            uint32_t ah[4], al[4];
            uint32_t aOff = SMEM_SWIZZLE_128B(
                (uint32_t)((wm * 16 + aRow) * 128 + ks * 32 + aKb));
            LDSM_X4(ah[0], ah[1], ah[2], ah[3], aHiA + aOff);
            LDSM_X4(al[0], al[1], al[2], al[3], aLoA + aOff);
            uint32_t bh[4][2], bl[4][2];
#pragma unroll
            for (int np = 0; np < 2; np++) {
                int nb = wn * 32 + np * 16;
                uint32_t bOff = SMEM_SWIZZLE_128B(
                    (uint32_t)((nb + bRow) * 128 + ks * 32 + bKb));
                LDSM_X4(bh[2 * np][0], bh[2 * np][1], bh[2 * np + 1][0], bh[2 * np + 1][1],
                        xHiA + bOff);
                LDSM_X4(bl[2 * np][0], bl[2 * np][1], bl[2 * np + 1][0], bl[2 * np + 1][1],
                        xLoA + bOff);
            }
#pragma unroll
            for (int nt = 0; nt < 4; nt++) {
                mma16816(acc[nt], ah, bh[nt]);
                mma16816(acc[nt], al, bh[nt]);
                mma16816(acc[nt], ah, bl[nt]);
            }
        }

        __nv_bfloat16* Yhi = Yh + (size_t)i * NNODE * 128;
        __nv_bfloat16* Yli = Yl + (size_t)i * NNODE * 128;
#pragma unroll
        for (int half = 0; half < 2; half++) {
            int r = wm * 16 + g + half * 8;
            size_t rofs = (size_t)r * 131072;
#pragma unroll
            for (int nt = 0; nt < 4; nt++) {
                int col = col0 + wn * 32 + nt * 8 + t4 * 2;
                uint32_t hp, lp;
                bf16split2(acc[nt][half * 2 + 0], acc[nt][half * 2 + 1], hp, lp);
                *(uint32_t*)(Yhi + rofs + col) = hp;
                *(uint32_t*)(Yli + rofs + col) = lp;
            }
        }
    }
}

// ---------------- k_mma: cp.async double-buffered 64x64 GEMM ------------------
// C[65536 x NOUT] = Acat @ Wt^T. A sources are pre-split bf16 hi/lo arrays.
// dynamic smem: 2 stages x (Ah 8K | Al 8K | Bh 8K | Bl 8K) = 64 KB.
// MODE 0: fp32 C (raw H). MODE 1: relu(+bias) -> Chi/Clo pair. MODE 2: +bias -> fp32 C.
template <int NOUT, int MODE>
__global__ void __launch_bounds__(256) k_mma(
    const __nv_bfloat16* __restrict__ a0h, const __nv_bfloat16* __restrict__ a0l,
    const __nv_bfloat16* __restrict__ a1h, const __nv_bfloat16* __restrict__ a1l,
    const __nv_bfloat16* __restrict__ wtHi, const __nv_bfloat16* __restrict__ wtLo,
    const float* __restrict__ bias, float* __restrict__ C,
    __nv_bfloat16* __restrict__ Chi, __nv_bfloat16* __restrict__ Clo, int nChunks)
{
    extern __shared__ __align__(16) unsigned char dynsm[];
    const uint32_t base = smem_to_u32(dynsm);
    int tid = threadIdx.x, lane = tid & 31, wid = tid >> 5;
    int wm = wid & 3, wn = wid >> 2;
    int row0 = blockIdx.x * 64;
    int n0   = blockIdx.y * 64;
    int Ktot = nChunks * 64;
    int g = lane >> 2, t4 = lane & 3;
    int aRow = lane & 15;
    int aKb  = (lane >> 4) * 16;
    int bRow = ((lane >> 4) << 3) + (lane & 7);
    int bKb  = ((lane >> 3) & 1) * 16;
    // per-thread fill coordinates (16B units; 8 units per 128B row)
    int fr0 = tid >> 3, fu0 = tid & 7;          // idx = tid
    int fr1 = (tid + 256) >> 3, fu1 = tid & 7;  // idx = tid + 256

    auto fill = [&](int stage, int c) {
        const __nv_bfloat16 *sh, *sl;
        int kk;
        if (c < 2) { sh = a0h; sl = a0l; kk = c * 64; }
        else {
            size_t off = (size_t)((c - 2) >> 1) * ((size_t)NNODE * 128);
            sh = a1h + off; sl = a1l + off; kk = (c & 1) * 64;
        }
        int kb = c * 64;
        uint32_t sb = base + stage * 32768;
        // A hi/lo: rows = nodes
        {
            size_t s0 = (size_t)(row0 + fr0) * 128 + kk + fu0 * 8;
            size_t s1 = (size_t)(row0 + fr1) * 128 + kk + fu1 * 8;
            uint32_t d0 = SMEM_SWIZZLE_128B((uint32_t)(fr0 * 128 + fu0 * 16));
            uint32_t d1 = SMEM_SWIZZLE_128B((uint32_t)(fr1 * 128 + fu1 * 16));
            CP16(sb + d0, sh + s0);
            CP16(sb + d1, sh + s1);
            CP16(sb + 8192 + d0, sl + s0);
            CP16(sb + 8192 + d1, sl + s1);
        }
        // B hi/lo: rows = output features
        {
            size_t s0 = (size_t)(n0 + fr0) * Ktot + kb + fu0 * 8;
            size_t s1 = (size_t)(n0 + fr1) * Ktot + kb + fu1 * 8;
            uint32_t d0 = SMEM_SWIZZLE_128B((uint32_t)(fr0 * 128 + fu0 * 16));
            uint32_t d1 = SMEM_SWIZZLE_128B((uint32_t)(fr1 * 128 + fu1 * 16));
            CP16(sb + 16384 + d0, wtHi + s0);
            CP16(sb + 16384 + d1, wtHi + s1);
            CP16(sb + 24576 + d0, wtLo + s0);
            CP16(sb + 24576 + d1, wtLo + s1);
        }
        CP_COMMIT();
    };

    float acc[4][4] = {};
    fill(0, 0);
    for (int c = 0; c < nChunks; c++) {
        if (c + 1 < nChunks) { fill((c + 1) & 1, c + 1); CP_WAIT1(); }
        else                 { CP_WAIT0(); }
        __syncthreads();
        uint32_t sb = base + (c & 1) * 32768;
        uint32_t aHiA = sb, aLoA = sb + 8192, bHiA = sb + 16384, bLoA = sb + 24576;
#pragma unroll
        for (int ks = 0; ks < 4; ks++) {
            uint32_t ah[4], al[4];
            uint32_t aOff = SMEM_SWIZZLE_128B(
                (uint32_t)((wm * 16 + aRow) * 128 + ks * 32 + aKb));
            LDSM_X4(ah[0], ah[1], ah[2], ah[3], aHiA + aOff);
            LDSM_X4(al[0], al[1], al[2], al[3], aLoA + aOff);
            uint32_t bh[4][2], bl[4][2];
#pragma unroll
            for (int np = 0; np < 2; np++) {
                int nb = wn * 32 + np * 16;
                uint32_t bOff = SMEM_SWIZZLE_128B(
                    (uint32_t)((nb + bRow) * 128 + ks * 32 + bKb));
                LDSM_X4(bh[2 * np][0], bh[2 * np][1], bh[2 * np + 1][0], bh[2 * np + 1][1],
                        bHiA + bOff);
                LDSM_X4(bl[2 * np][0], bl[2 * np][1], bl[2 * np + 1][0], bl[2 * np + 1][1],
                        bLoA + bOff);
            }
#pragma unroll
            for (int nt = 0; nt < 4; nt++) {
                mma16816(acc[nt], ah, bh[nt]);
                mma16816(acc[nt], al, bh[nt]);
                mma16816(acc[nt], ah, bl[nt]);
            }
        }
        __syncthreads();   // all warps done with this stage before it is refilled
    }

#pragma unroll
    for (int half = 0; half < 2; half++) {
        int r = row0 + wm * 16 + g + half * 8;
#pragma unroll
        for (int nt = 0; nt < 4; nt++) {
            int col = n0 + wn * 32 + nt * 8 + t4 * 2;
            float v0 = acc[nt][half * 2 + 0];
            float v1 = acc[nt][half * 2 + 1];
            if (MODE >= 1) {
                v0 += bias[col]; v1 += bias[col + 1];
                if (MODE == 1) { v0 = fmaxf(v0, 0.f); v1 = fmaxf(v1, 0.f); }
            }
            if (MODE == 1) {
                uint32_t hp, lp;
                bf16split2(v0, v1, hp, lp);
                *(uint32_t*)(Chi + (size_t)r * NOUT + col) = hp;
                *(uint32_t*)(Clo + (size_t)r * NOUT + col) = lp;
            } else {
                *(float2*)(C + (size_t)r * NOUT + col) = make_float2(v0, v1);
            }
        }
    }
}

// ---------------- edge aggregation: fp32 in, bf16-pair out --------------------
__global__ void __launch_bounds__(256) k_agg(const float* __restrict__ H,
                                             const float* __restrict__ bsum,
                                             __nv_bfloat16* __restrict__ outH,
                                             __nv_bfloat16* __restrict__ outL) {
    int v = (blockIdx.x * 256 + threadIdx.x) >> 5;
    int lane = threadIdx.x & 31;
    if (v >= NNODE) return;
    float dv = g_dinv[v];
    float4 zv = *((const float4*)(H + (size_t)v * 128) + lane);
    float4 acc = make_float4(dv * zv.x, dv * zv.y, dv * zv.z, dv * zv.w);
    int p = g_rowptr[v], p1 = g_rowptr[v + 1];
    for (; p + 3 < p1; p += 4) {
        int u0 = g_csr[p], u1 = g_csr[p + 1], u2 = g_csr[p + 2], u3 = g_csr[p + 3];
        float d0 = g_dinv[u0], d1 = g_dinv[u1], d2 = g_dinv[u2], d3 = g_dinv[u3];
        float4 z0 = *((const float4*)(H + (size_t)u0 * 128) + lane);
        float4 z1 = *((const float4*)(H + (size_t)u1 * 128) + lane);
        float4 z2 = *((const float4*)(H + (size_t)u2 * 128) + lane);
        float4 z3 = *((const float4*)(H + (size_t)u3 * 128) + lane);
        acc.x += d0 * z0.x + d1 * z1.x + d2 * z2.x + d3 * z3.x;
        acc.y += d0 * z0.y + d1 * z1.y + d2 * z2.y + d3 * z3.y;
        acc.z += d0 * z0.z + d1 * z1.z + d2 * z2.z + d3 * z3.z;
        acc.w += d0 * z0.w + d1 * z1.w + d2 * z2.w + d3 * z3.w;
    }
    for (; p < p1; p++) {
        int u = g_csr[p];
        float du = g_dinv[u];
        float4 z = *((const float4*)(H + (size_t)u * 128) + lane);
        acc.x += du * z.x; acc.y += du * z.y;
        acc.z += du * z.z; acc.w += du * z.w;
    }
    float4 b = *((const float4*)bsum + lane);
    float4 o;
    o.x = fmaxf(dv * acc.x + b.x, 0.f);
    o.y = fmaxf(dv * acc.y + b.y, 0.f);
    o.z = fmaxf(dv * acc.z + b.z, 0.f);
    o.w = fmaxf(dv * acc.w + b.w, 0.f);
    uint2 hp, lp;
    bf16split4(o, hp, lp);
    *(uint2*)(outH + (size_t)v * 128 + lane * 4) = hp;
    *(uint2*)(outL + (size_t)v * 128 + lane * 4) = lp;
}

// ---------------- host orchestration -----------------------------------------
extern "C" void kernel_launch(void* const* d_in, const int* in_sizes, int n_in,
                              void* d_out, int out_size) {
    const float* x    = (const float*)d_in[0];
    const int*   sub  = (const int*)d_in[1];
    const float* adj  = (const float*)d_in[2];
    const float* gcnW = (const float*)d_in[3];
    const float* gcnB = (const float*)d_in[4];
    const float* W1   = (const float*)d_in[5];
    const float* b1   = (const float*)d_in[6];
    const float* W2   = (const float*)d_in[7];
    const float* b2   = (const float*)d_in[8];
    float* out = (float*)d_out;

    void* p;
    float *pZ, *pB;
    __nv_bfloat16 *pYh, *pYl, *pXh, *pXl;
    __nv_bfloat16 *pWLh, *pWLl, *pW1h, *pW1l, *pW2h, *pW2l;
    cudaGetSymbolAddress(&p, g_Z);    pZ  = (float*)p;
    cudaGetSymbolAddress(&p, g_bsum); pB  = (float*)p;
    cudaGetSymbolAddress(&p, g_Yhi);  pYh = (__nv_bfloat16*)p;
    cudaGetSymbolAddress(&p, g_Ylo);  pYl = (__nv_bfloat16*)p;
    cudaGetSymbolAddress(&p, g_Xhi);  pXh = (__nv_bfloat16*)p;
    cudaGetSymbolAddress(&p, g_Xlo);  pXl = (__nv_bfloat16*)p;
    cudaGetSymbolAddress(&p, g_WLhi); pWLh = (__nv_bfloat16*)p;
    cudaGetSymbolAddress(&p, g_WLlo); pWLl = (__nv_bfloat16*)p;
    cudaGetSymbolAddress(&p, g_W1hi); pW1h = (__nv_bfloat16*)p;
    cudaGetSymbolAddress(&p, g_W1lo); pW1l = (__nv_bfloat16*)p;
    cudaGetSymbolAddress(&p, g_W2hi); pW2h = (__nv_bfloat16*)p;
    cudaGetSymbolAddress(&p, g_W2lo); pW2l = (__nv_bfloat16*)p;

    const int DSM = 65536;
    cudaFuncSetAttribute(k_mma<128, 0>, cudaFuncAttributeMaxDynamicSharedMemorySize, DSM);
    cudaFuncSetAttribute(k_mma<128, 1>, cudaFuncAttributeMaxDynamicSharedMemorySize, DSM);
    cudaFuncSetAttribute(k_mma<64, 2>,  cudaFuncAttributeMaxDynamicSharedMemorySize, DSM);

    // deps of first k_mma; slot 4 = k_mixmma (profiled)
    k_xprep<<<NNODE * 128 / 4 / 256, 256>>>(x);                             // 1
    k_metaprep<<<1, 1024>>>(adj);                                           // 2
    k_wprep<<<(512 * 128 + 255) / 256, 256>>>(gcnW, pWLh, pWLl, 512, 128);  // 3
    k_mixmma<<<2048, 256>>>(pXh, pXl, pYh, pYl);                            // 4 <- ncu
    k_mma<128, 0><<<dim3(1024, 2), 256, DSM>>>(pXh, pXl, pYh, pYl,
                                               pWLh, pWLl, nullptr, pZ,
                                               nullptr, nullptr, 8);

    // graph preprocessing (needed before first k_agg)
    k_init<<<256, 256>>>();
    k_hist<<<NEDGE / 256, 256>>>(sub + NEDGE);
    k_scan_partial<<<256, 256>>>();
    k_scan_block<<<1, 256>>>();
    k_scan_final<<<256, 256>>>();
    k_fill<<<NEDGE / 256, 256>>>(sub, sub + NEDGE);
    // remaining weight prep
    k_wprep<<<(512 * 128 + 255) / 256, 256>>>(gcnW + 65536, pWLh + 65536, pWLl + 65536, 512, 128);
    k_wprep<<<(512 * 128 + 255) / 256, 256>>>(gcnW + 131072, pWLh + 131072, pWLl + 131072, 512, 128);
    k_wprep<<<(128 * 128 + 255) / 256, 256>>>(W1, pW1h, pW1l, 128, 128);
    k_wprep<<<(128 * 64 + 255) / 256, 256>>>(W2, pW2h, pW2l, 128, 64);
    k_bsum<<<2, 256>>>(gcnB);

    // layer 0 aggregation (writes X pair for next layer)
    k_agg<<<NNODE / 8, 256>>>(pZ, pB, pXh, pXl);
    // layers 1..2
    for (int l = 1; l < NLAYER; l++) {
        k_mixmma<<<2048, 256>>>(pXh, pXl, pYh, pYl);
        k_mma<128, 0><<<dim3(1024, 2), 256, DSM>>>(pXh, pXl, pYh, pYl,
                                                   pWLh + (size_t)l * 65536,
                                                   pWLl + (size_t)l * 65536,
                                                   nullptr, pZ, nullptr, nullptr, 8);
        k_agg<<<NNODE / 8, 256>>>(pZ, pB + l * 128, pXh, pXl);
    }
    // MLP head: head1 -> Y0 pair (scratch), head2 -> out
    k_mma<128, 1><<<dim3(1024, 2), 256, DSM>>>(pXh, pXl, nullptr, nullptr,
                                               pW1h, pW1l, b1, nullptr, pYh, pYl, 2);
    k_mma<64, 2><<<dim3(1024, 1), 256, DSM>>>(pYh, pYl, nullptr, nullptr,
                                              pW2h, pW2l, b2, out, nullptr, nullptr, 2);
}

// round 15
// speedup vs baseline: 1.2989x; 1.0076x over previous
#include <cuda_runtime.h>
#include <cuda_bf16.h>
#include <cstdint>

#define NNODE 65536
#define NEDGE 1048576
#define NLAYER 3

// ---------------- scratch (static device globals) ---------------------------
__device__ float g_dinv[NNODE];
__device__ int   g_indeg[NNODE];
__device__ int   g_rowptr[NNODE + 1];
__device__ int   g_cursor[NNODE];
__device__ int   g_csr[NEDGE];
__device__ int   g_part[256];
__device__ float g_A[3][64 * 64];
__device__ __nv_bfloat16 g_Ahi[3 * 4096], g_Alo[3 * 4096];
__device__ float g_bsum[NLAYER][128];
__device__ float g_Z[(size_t)NNODE * 128];                       // raw H (fp32 for agg)
__device__ __nv_bfloat16 g_Yhi[(size_t)3 * NNODE * 128];
__device__ __nv_bfloat16 g_Ylo[(size_t)3 * NNODE * 128];
__device__ __nv_bfloat16 g_Xhi[(size_t)NNODE * 128];
__device__ __nv_bfloat16 g_Xlo[(size_t)NNODE * 128];
__device__ __nv_bfloat16 g_WLhi[3][128 * 512], g_WLlo[3][128 * 512];
__device__ __nv_bfloat16 g_W1hi[128 * 128],    g_W1lo[128 * 128];
__device__ __nv_bfloat16 g_W2hi[64 * 128],     g_W2lo[64 * 128];

// ================= helpers ====================================================
__device__ __forceinline__ uint32_t smem_to_u32(const void* p) {
    uint32_t a;
    asm("{ .reg .u64 t; cvta.to.shared.u64 t, %1; cvt.u32.u64 %0, t; }" : "=r"(a) : "l"(p));
    return a;
}
#define SMEM_SWIZZLE_128B(o) ((o) ^ (((o) >> 3) & 0x70))

#define LDSM_X4(r0, r1, r2, r3, addr) \
    asm volatile("ldmatrix.sync.aligned.m8n8.x4.shared.b16 {%0,%1,%2,%3}, [%4];" \
                 : "=r"(r0), "=r"(r1), "=r"(r2), "=r"(r3) : "r"(addr))

#define CP16(dst, src) \
    asm volatile("cp.async.cg.shared.global [%0], [%1], 16;" :: "r"(dst), "l"(src))
#define CP_COMMIT() asm volatile("cp.async.commit_group;" ::: "memory")
#define CP_WAIT1()  asm volatile("cp.async.wait_group 1;" ::: "memory")
#define CP_WAIT0()  asm volatile("cp.async.wait_group 0;" ::: "memory")

__device__ __forceinline__ void mma16816(float* c, const uint32_t* a, const uint32_t* b) {
    asm volatile(
        "mma.sync.aligned.m16n8k16.row.col.f32.bf16.bf16.f32 "
        "{%0,%1,%2,%3}, {%4,%5,%6,%7}, {%8,%9}, {%0,%1,%2,%3};"
        : "+f"(c[0]), "+f"(c[1]), "+f"(c[2]), "+f"(c[3])
        : "r"(a[0]), "r"(a[1]), "r"(a[2]), "r"(a[3]), "r"(b[0]), "r"(b[1]));
}

__device__ __forceinline__ void bf16split4(float4 v, uint2& hp, uint2& lp) {
    __nv_bfloat16 h0 = __float2bfloat16(v.x), h1 = __float2bfloat16(v.y);
    __nv_bfloat16 h2 = __float2bfloat16(v.z), h3 = __float2bfloat16(v.w);
    __nv_bfloat16 l0 = __float2bfloat16(v.x - __bfloat162float(h0));
    __nv_bfloat16 l1 = __float2bfloat16(v.y - __bfloat162float(h1));
    __nv_bfloat16 l2 = __float2bfloat16(v.z - __bfloat162float(h2));
    __nv_bfloat16 l3 = __float2bfloat16(v.w - __bfloat162float(h3));
    hp.x = (uint32_t)*(unsigned short*)&h0 | ((uint32_t)*(unsigned short*)&h1 << 16);
    hp.y = (uint32_t)*(unsigned short*)&h2 | ((uint32_t)*(unsigned short*)&h3 << 16);
    lp.x = (uint32_t)*(unsigned short*)&l0 | ((uint32_t)*(unsigned short*)&l1 << 16);
    lp.y = (uint32_t)*(unsigned short*)&l2 | ((uint32_t)*(unsigned short*)&l3 << 16);
}
__device__ __forceinline__ void bf16split2(float v0, float v1, uint32_t& hp, uint32_t& lp) {
    __nv_bfloat16 h0 = __float2bfloat16(v0), h1 = __float2bfloat16(v1);
    __nv_bfloat16 l0 = __float2bfloat16(v0 - __bfloat162float(h0));
    __nv_bfloat16 l1 = __float2bfloat16(v1 - __bfloat162float(h1));
    hp = (uint32_t)*(unsigned short*)&h0 | ((uint32_t)*(unsigned short*)&h1 << 16);
    lp = (uint32_t)*(unsigned short*)&l0 | ((uint32_t)*(unsigned short*)&l1 << 16);
}

// ---------------- graph preprocessing ---------------------------------------
__global__ void k_init() {
    int i = blockIdx.x * blockDim.x + threadIdx.x;
    if (i < NNODE) { g_indeg[i] = 0; g_cursor[i] = 0; }
}
__global__ void k_hist(const int* __restrict__ dst) {
    int e = blockIdx.x * blockDim.x + threadIdx.x;
    if (e < NEDGE) atomicAdd(&g_indeg[dst[e]], 1);
}
__global__ void k_scan_partial() {
    __shared__ int sh[256];
    int b = blockIdx.x, t = threadIdx.x;
    sh[t] = g_indeg[b * 256 + t];
    __syncthreads();
    for (int s = 128; s > 0; s >>= 1) {
        if (t < s) sh[t] += sh[t + s];
        __syncthreads();
    }
    if (t == 0) g_part[b] = sh[0];
}
__global__ void k_scan_block() {
    __shared__ int sh[256];
    int t = threadIdx.x;
    int v = g_part[t];
    sh[t] = v;
    __syncthreads();
    for (int off = 1; off < 256; off <<= 1) {
        int xv = (t >= off) ? sh[t - off] : 0;
        __syncthreads();
        sh[t] += xv;
        __syncthreads();
    }
    g_part[t] = sh[t] - v;
}
__global__ void k_scan_final() {
    __shared__ int sh[256];
    int b = blockIdx.x, t = threadIdx.x;
    int v = g_indeg[b * 256 + t];
    sh[t] = v;
    __syncthreads();
    for (int off = 1; off < 256; off <<= 1) {
        int xv = (t >= off) ? sh[t - off] : 0;
        __syncthreads();
        sh[t] += xv;
        __syncthreads();
    }
    int excl = sh[t] - v + g_part[b];
    g_rowptr[b * 256 + t] = excl;
    if (b == 255 && t == 255) g_rowptr[NNODE] = excl + v;
    g_dinv[b * 256 + t] = rsqrtf((float)(v + 1));
}
__global__ void k_fill(const int* __restrict__ src, const int* __restrict__ dst) {
    int e = blockIdx.x * blockDim.x + threadIdx.x;
    if (e < NEDGE) {
        int d = dst[e];
        int p = atomicAdd(&g_cursor[d], 1);
        g_csr[g_rowptr[d] + p] = src[e];
    }
}

// ---------------- fused meta prep --------------------------------------------
__global__ void __launch_bounds__(1024) k_metaprep(const float* __restrict__ adj) {
    float* Af = &g_A[0][0];
    int tid = threadIdx.x;
    for (int i = tid; i < 4096; i += 1024) Af[i] = adj[i];
    __syncthreads();
    {
        int c = tid & 63;
        for (int r = tid >> 6; r < 64; r += 16) {
            float s = 0.f;
#pragma unroll 16
            for (int k = 0; k < 64; k++) s += Af[r * 64 + k] * Af[k * 64 + c];
            Af[4096 + r * 64 + c] = s;
        }
    }
    __syncthreads();
    {
        int c = tid & 63;
        for (int r = tid >> 6; r < 64; r += 16) {
            float s = 0.f;
#pragma unroll 16
            for (int k = 0; k < 64; k++) s += Af[4096 + r * 64 + k] * Af[k * 64 + c];
            Af[8192 + r * 64 + c] = s;
        }
    }
    __syncthreads();
    for (int i = tid; i < 3 * 4096; i += 1024) {
        float v = Af[i];
        __nv_bfloat16 h = __float2bfloat16(v);
        g_Ahi[i] = h;
        g_Alo[i] = __float2bfloat16(v - __bfloat162float(h));
    }
}
__global__ void k_bsum(const float* __restrict__ gb) {
    int i = blockIdx.x * blockDim.x + threadIdx.x;
    if (i < NLAYER * 128) {
        int l = i / 128, c = i % 128;
        float s = 0.f;
        for (int j = 0; j < 4; j++) s += gb[(l * 4 + j) * 128 + c];
        g_bsum[l][c] = s;
    }
}

// weight prep: W[K x N] -> Wt_hi/lo[n][k]
__global__ void k_wprep(const float* __restrict__ W, __nv_bfloat16* __restrict__ hi,
                        __nv_bfloat16* __restrict__ lo, int K, int N) {
    int idx = blockIdx.x * 256 + threadIdx.x;
    if (idx >= K * N) return;
    int n = idx / K, k = idx % K;
    float v = W[(size_t)k * N + n];
    __nv_bfloat16 h = __float2bfloat16(v);
    hi[idx] = h;
    lo[idx] = __float2bfloat16(v - __bfloat162float(h));
}

// x fp32 -> Xhi/Xlo bf16 split (one-time, layer 0)
__global__ void k_xprep(const float* __restrict__ x) {
    int idx = blockIdx.x * 256 + threadIdx.x;
    float4 v = *((const float4*)x + idx);
    uint2 hp, lp;
    bf16split4(v, hp, lp);
    *((uint2*)g_Xhi + idx) = hp;
    *((uint2*)g_Xlo + idx) = lp;
}

// ---------------- HMMA mix (ks-outer / i-inner, B frags loaded once per ks) ---
// Y_i = A_i @ X, i=0..2. Dynamic smem 64KB:
//   [Xh 8K][Xl 8K][Ah0 Ah1 Ah2 24K][Al0 Al1 Al2 24K]
// The transpose stage reuses the A region (disjoint lifetime).
__global__ void __launch_bounds__(256) k_mixmma(const __nv_bfloat16* __restrict__ Xh,
                                                const __nv_bfloat16* __restrict__ Xl,
                                                __nv_bfloat16* __restrict__ Yh,
                                                __nv_bfloat16* __restrict__ Yl) {
    extern __shared__ __align__(1024) unsigned char dynsm[];
    const uint32_t base = smem_to_u32(dynsm);
    const uint32_t xHiA = base, xLoA = base + 8192;
    const uint32_t aHi0 = base + 16384, aLo0 = base + 40960;
    unsigned short (*sStH)[68] = (unsigned short (*)[68])(dynsm + 16384);
    unsigned short (*sStL)[68] = (unsigned short (*)[68])(dynsm + 16384 + 4608);
    unsigned char* sXh = dynsm;
    unsigned char* sXl = dynsm + 8192;
    int tid = threadIdx.x, lane = tid & 31, wid = tid >> 5;
    int wm = wid & 3, wn = wid >> 2;
    int col0 = blockIdx.x * 64;
    int g = lane >> 2, t4 = lane & 3;
    int aRow = lane & 15, aKb = (lane >> 4) * 16;
    int bRow = ((lane >> 4) << 3) + (lane & 7);
    int bKb  = ((lane >> 3) & 1) * 16;

    // X tile 64(j) x 64(col) bf16 pair: stage 32 rows, transpose, store swizzled
#pragma unroll
    for (int hh = 0; hh < 2; hh++) {
#pragma unroll
        for (int q = 0; q < 2; q++) {
            int idx = tid + 256 * q;
            int jj = idx >> 4, c4 = (idx & 15) * 4;
            size_t gofs = (size_t)(hh * 32 + jj) * 131072 + col0 + c4;
            *(uint2*)&sStH[jj][c4] = *(const uint2*)(Xh + gofs);
            *(uint2*)&sStL[jj][c4] = *(const uint2*)(Xl + gofs);
        }
        __syncthreads();
#pragma unroll
        for (int q = 0; q < 2; q++) {
            int idx = tid + 256 * q;
            int col = idx & 63, j4 = idx >> 6;
            uint2 hp, lp;
            hp.x = (uint32_t)sStH[j4 * 4 + 0][col] | ((uint32_t)sStH[j4 * 4 + 1][col] << 16);
            hp.y = (uint32_t)sStH[j4 * 4 + 2][col] | ((uint32_t)sStH[j4 * 4 + 3][col] << 16);
            lp.x = (uint32_t)sStL[j4 * 4 + 0][col] | ((uint32_t)sStL[j4 * 4 + 1][col] << 16);
            lp.y = (uint32_t)sStL[j4 * 4 + 2][col] | ((uint32_t)sStL[j4 * 4 + 3][col] << 16);
            uint32_t sw = SMEM_SWIZZLE_128B((uint32_t)(col * 128 + (hh * 32 + j4 * 4) * 2));
            *(uint2*)(sXh + sw) = hp;
            *(uint2*)(sXl + sw) = lp;
        }
        __syncthreads();
    }

    // load ALL 3 A_i tiles (hi/lo) into smem: 3 x 1024 uint2 units
#pragma unroll
    for (int q = 0; q < 12; q++) {
        int idx = tid + 256 * q;               // 0..3071
        int i = idx >> 10, rc = idx & 1023;
        int row = rc >> 4, k4 = (rc & 15) * 4;
        uint2 h = *(const uint2*)(g_Ahi + i * 4096 + row * 64 + k4);
        uint2 l = *(const uint2*)(g_Alo + i * 4096 + row * 64 + k4);
        uint32_t sw = SMEM_SWIZZLE_128B((uint32_t)(row * 128 + k4 * 2));
        *(uint2*)(dynsm + 16384 + i * 8192 + sw) = h;
        *(uint2*)(dynsm + 40960 + i * 8192 + sw) = l;
    }
    __syncthreads();

    float acc[3][4][4] = {};
#pragma unroll
    for (int ks = 0; ks < 4; ks++) {
        // B (X) fragments: loaded ONCE per ks, shared by all 3 i
        uint32_t bh[4][2], bl[4][2];
#pragma unroll
        for (int np = 0; np < 2; np++) {
            int nb = wn * 32 + np * 16;
            uint32_t bOff = SMEM_SWIZZLE_128B(
                (uint32_t)((nb + bRow) * 128 + ks * 32 + bKb));
            LDSM_X4(bh[2 * np][0], bh[2 * np][1], bh[2 * np + 1][0], bh[2 * np + 1][1],
                    xHiA + bOff);
            LDSM_X4(bl[2 * np][0], bl[2 * np][1], bl[2 * np + 1][0], bl[2 * np + 1][1],
                    xLoA + bOff);
        }
        uint32_t aOff = SMEM_SWIZZLE_128B(
            (uint32_t)((wm * 16 + aRow) * 128 + ks * 32 + aKb));
#pragma unroll
        for (int i = 0; i < 3; i++) {
            uint32_t ah[4], al[4];
            LDSM_X4(ah[0], ah[1], ah[2], ah[3], aHi0 + i * 8192 + aOff);
            LDSM_X4(al[0], al[1], al[2], al[3], aLo0 + i * 8192 + aOff);
#pragma unroll
            for (int nt = 0; nt < 4; nt++) {
                mma16816(acc[i][nt], ah, bh[nt]);
                mma16816(acc[i][nt], al, bh[nt]);
                mma16816(acc[i][nt], ah, bl[nt]);
            }
        }
    }

#pragma unroll
    for (int i = 0; i < 3; i++) {
        __nv_bfloat16* Yhi = Yh + (size_t)i * NNODE * 128;
        __nv_bfloat16* Yli = Yl + (size_t)i * NNODE * 128;
#pragma unroll
        for (int half = 0; half < 2; half++) {
            int r = wm * 16 + g + half * 8;
            size_t rofs = (size_t)r * 131072;
#pragma unroll
            for (int nt = 0; nt < 4; nt++) {
                int col = col0 + wn * 32 + nt * 8 + t4 * 2;
                uint32_t hp, lp;
                bf16split2(acc[i][nt][half * 2 + 0], acc[i][nt][half * 2 + 1], hp, lp);
                *(uint32_t*)(Yhi + rofs + col) = hp;
                *(uint32_t*)(Yli + rofs + col) = lp;
            }
        }
    }
}

// ---------------- k_mma: cp.async double-buffered 64x64 GEMM ------------------
template <int NOUT, int MODE>
__global__ void __launch_bounds__(256) k_mma(
    const __nv_bfloat16* __restrict__ a0h, const __nv_bfloat16* __restrict__ a0l,
    const __nv_bfloat16* __restrict__ a1h, const __nv_bfloat16* __restrict__ a1l,
    const __nv_bfloat16* __restrict__ wtHi, const __nv_bfloat16* __restrict__ wtLo,
    const float* __restrict__ bias, float* __restrict__ C,
    __nv_bfloat16* __restrict__ Chi, __nv_bfloat16* __restrict__ Clo, int nChunks)
{
    extern __shared__ __align__(16) unsigned char dynsm[];
    const uint32_t base = smem_to_u32(dynsm);
    int tid = threadIdx.x, lane = tid & 31, wid = tid >> 5;
    int wm = wid & 3, wn = wid >> 2;
    int row0 = blockIdx.x * 64;
    int n0   = blockIdx.y * 64;
    int Ktot = nChunks * 64;
    int g = lane >> 2, t4 = lane & 3;
    int aRow = lane & 15;
    int aKb  = (lane >> 4) * 16;
    int bRow = ((lane >> 4) << 3) + (lane & 7);
    int bKb  = ((lane >> 3) & 1) * 16;
    int fr0 = tid >> 3, fu0 = tid & 7;
    int fr1 = (tid + 256) >> 3, fu1 = tid & 7;

    auto fill = [&](int stage, int c) {
        const __nv_bfloat16 *sh, *sl;
        int kk;
        if (c < 2) { sh = a0h; sl = a0l; kk = c * 64; }
        else {
            size_t off = (size_t)((c - 2) >> 1) * ((size_t)NNODE * 128);
            sh = a1h + off; sl = a1l + off; kk = (c & 1) * 64;
        }
        int kb = c * 64;
        uint32_t sb = base + stage * 32768;
        {
            size_t s0 = (size_t)(row0 + fr0) * 128 + kk + fu0 * 8;
            size_t s1 = (size_t)(row0 + fr1) * 128 + kk + fu1 * 8;
            uint32_t d0 = SMEM_SWIZZLE_128B((uint32_t)(fr0 * 128 + fu0 * 16));
            uint32_t d1 = SMEM_SWIZZLE_128B((uint32_t)(fr1 * 128 + fu1 * 16));
            CP16(sb + d0, sh + s0);
            CP16(sb + d1, sh + s1);
            CP16(sb + 8192 + d0, sl + s0);
            CP16(sb + 8192 + d1, sl + s1);
        }
        {
            size_t s0 = (size_t)(n0 + fr0) * Ktot + kb + fu0 * 8;
            size_t s1 = (size_t)(n0 + fr1) * Ktot + kb + fu1 * 8;
            uint32_t d0 = SMEM_SWIZZLE_128B((uint32_t)(fr0 * 128 + fu0 * 16));
            uint32_t d1 = SMEM_SWIZZLE_128B((uint32_t)(fr1 * 128 + fu1 * 16));
            CP16(sb + 16384 + d0, wtHi + s0);
            CP16(sb + 16384 + d1, wtHi + s1);
            CP16(sb + 24576 + d0, wtLo + s0);
            CP16(sb + 24576 + d1, wtLo + s1);
        }
        CP_COMMIT();
    };

    float acc[4][4] = {};
    fill(0, 0);
    for (int c = 0; c < nChunks; c++) {
        if (c + 1 < nChunks) { fill((c + 1) & 1, c + 1); CP_WAIT1(); }
        else                 { CP_WAIT0(); }
        __syncthreads();
        uint32_t sb = base + (c & 1) * 32768;
        uint32_t aHiA = sb, aLoA = sb + 8192, bHiA = sb + 16384, bLoA = sb + 24576;
#pragma unroll
        for (int ks = 0; ks < 4; ks++) {
            uint32_t ah[4], al[4];
            uint32_t aOff = SMEM_SWIZZLE_128B(
                (uint32_t)((wm * 16 + aRow) * 128 + ks * 32 + aKb));
            LDSM_X4(ah[0], ah[1], ah[2], ah[3], aHiA + aOff);
            LDSM_X4(al[0], al[1], al[2], al[3], aLoA + aOff);
            uint32_t bh[4][2], bl[4][2];
#pragma unroll
            for (int np = 0; np < 2; np++) {
                int nb = wn * 32 + np * 16;
                uint32_t bOff = SMEM_SWIZZLE_128B(
                    (uint32_t)((nb + bRow) * 128 + ks * 32 + bKb));
                LDSM_X4(bh[2 * np][0], bh[2 * np][1], bh[2 * np + 1][0], bh[2 * np + 1][1],
                        bHiA + bOff);
                LDSM_X4(bl[2 * np][0], bl[2 * np][1], bl[2 * np + 1][0], bl[2 * np + 1][1],
                        bLoA + bOff);
            }
#pragma unroll
            for (int nt = 0; nt < 4; nt++) {
                mma16816(acc[nt], ah, bh[nt]);
                mma16816(acc[nt], al, bh[nt]);
                mma16816(acc[nt], ah, bl[nt]);
            }
        }
        __syncthreads();
    }

#pragma unroll
    for (int half = 0; half < 2; half++) {
        int r = row0 + wm * 16 + g + half * 8;
#pragma unroll
        for (int nt = 0; nt < 4; nt++) {
            int col = n0 + wn * 32 + nt * 8 + t4 * 2;
            float v0 = acc[nt][half * 2 + 0];
            float v1 = acc[nt][half * 2 + 1];
            if (MODE >= 1) {
                v0 += bias[col]; v1 += bias[col + 1];
                if (MODE == 1) { v0 = fmaxf(v0, 0.f); v1 = fmaxf(v1, 0.f); }
            }
            if (MODE == 1) {
                uint32_t hp, lp;
                bf16split2(v0, v1, hp, lp);
                *(uint32_t*)(Chi + (size_t)r * NOUT + col) = hp;
                *(uint32_t*)(Clo + (size_t)r * NOUT + col) = lp;
            } else {
                *(float2*)(C + (size_t)r * NOUT + col) = make_float2(v0, v1);
            }
        }
    }
}

// ---------------- edge aggregation: fp32 in, bf16-pair out --------------------
__global__ void __launch_bounds__(256) k_agg(const float* __restrict__ H,
                                             const float* __restrict__ bsum,
                                             __nv_bfloat16* __restrict__ outH,
                                             __nv_bfloat16* __restrict__ outL) {
    int v = (blockIdx.x * 256 + threadIdx.x) >> 5;
    int lane = threadIdx.x & 31;
    if (v >= NNODE) return;
    float dv = g_dinv[v];
    float4 zv = *((const float4*)(H + (size_t)v * 128) + lane);
    float4 acc = make_float4(dv * zv.x, dv * zv.y, dv * zv.z, dv * zv.w);
    int p = g_rowptr[v], p1 = g_rowptr[v + 1];
    for (; p + 3 < p1; p += 4) {
        int u0 = g_csr[p], u1 = g_csr[p + 1], u2 = g_csr[p + 2], u3 = g_csr[p + 3];
        float d0 = g_dinv[u0], d1 = g_dinv[u1], d2 = g_dinv[u2], d3 = g_dinv[u3];
        float4 z0 = *((const float4*)(H + (size_t)u0 * 128) + lane);
        float4 z1 = *((const float4*)(H + (size_t)u1 * 128) + lane);
        float4 z2 = *((const float4*)(H + (size_t)u2 * 128) + lane);
        float4 z3 = *((const float4*)(H + (size_t)u3 * 128) + lane);
        acc.x += d0 * z0.x + d1 * z1.x + d2 * z2.x + d3 * z3.x;
        acc.y += d0 * z0.y + d1 * z1.y + d2 * z2.y + d3 * z3.y;
        acc.z += d0 * z0.z + d1 * z1.z + d2 * z2.z + d3 * z3.z;
        acc.w += d0 * z0.w + d1 * z1.w + d2 * z2.w + d3 * z3.w;
    }
    for (; p < p1; p++) {
        int u = g_csr[p];
        float du = g_dinv[u];
        float4 z = *((const float4*)(H + (size_t)u * 128) + lane);
        acc.x += du * z.x; acc.y += du * z.y;
        acc.z += du * z.z; acc.w += du * z.w;
    }
    float4 b = *((const float4*)bsum + lane);
    float4 o;
    o.x = fmaxf(dv * acc.x + b.x, 0.f);
    o.y = fmaxf(dv * acc.y + b.y, 0.f);
    o.z = fmaxf(dv * acc.z + b.z, 0.f);
    o.w = fmaxf(dv * acc.w + b.w, 0.f);
    uint2 hp, lp;
    bf16split4(o, hp, lp);
    *(uint2*)(outH + (size_t)v * 128 + lane * 4) = hp;
    *(uint2*)(outL + (size_t)v * 128 + lane * 4) = lp;
}

// ---------------- host orchestration -----------------------------------------
extern "C" void kernel_launch(void* const* d_in, const int* in_sizes, int n_in,
                              void* d_out, int out_size) {
    const float* x    = (const float*)d_in[0];
    const int*   sub  = (const int*)d_in[1];
    const float* adj  = (const float*)d_in[2];
    const float* gcnW = (const float*)d_in[3];
    const float* gcnB = (const float*)d_in[4];
    const float* W1   = (const float*)d_in[5];
    const float* b1   = (const float*)d_in[6];
    const float* W2   = (const float*)d_in[7];
    const float* b2   = (const float*)d_in[8];
    float* out = (float*)d_out;

    void* p;
    float *pZ, *pB;
    __nv_bfloat16 *pYh, *pYl, *pXh, *pXl;
    __nv_bfloat16 *pWLh, *pWLl, *pW1h, *pW1l, *pW2h, *pW2l;
    cudaGetSymbolAddress(&p, g_Z);    pZ  = (float*)p;
    cudaGetSymbolAddress(&p, g_bsum); pB  = (float*)p;
    cudaGetSymbolAddress(&p, g_Yhi);  pYh = (__nv_bfloat16*)p;
    cudaGetSymbolAddress(&p, g_Ylo);  pYl = (__nv_bfloat16*)p;
    cudaGetSymbolAddress(&p, g_Xhi);  pXh = (__nv_bfloat16*)p;
    cudaGetSymbolAddress(&p, g_Xlo);  pXl = (__nv_bfloat16*)p;
    cudaGetSymbolAddress(&p, g_WLhi); pWLh = (__nv_bfloat16*)p;
    cudaGetSymbolAddress(&p, g_WLlo); pWLl = (__nv_bfloat16*)p;
    cudaGetSymbolAddress(&p, g_W1hi); pW1h = (__nv_bfloat16*)p;
    cudaGetSymbolAddress(&p, g_W1lo); pW1l = (__nv_bfloat16*)p;
    cudaGetSymbolAddress(&p, g_W2hi); pW2h = (__nv_bfloat16*)p;
    cudaGetSymbolAddress(&p, g_W2lo); pW2l = (__nv_bfloat16*)p;

    const int DSM = 65536;
    cudaFuncSetAttribute(k_mma<128, 0>, cudaFuncAttributeMaxDynamicSharedMemorySize, DSM);
    cudaFuncSetAttribute(k_mma<128, 1>, cudaFuncAttributeMaxDynamicSharedMemorySize, DSM);
    cudaFuncSetAttribute(k_mma<64, 2>,  cudaFuncAttributeMaxDynamicSharedMemorySize, DSM);
    cudaFuncSetAttribute(k_mixmma,      cudaFuncAttributeMaxDynamicSharedMemorySize, DSM);

    // deps of first k_mma; slot 4 = k_mixmma (profiled)
    k_xprep<<<NNODE * 128 / 4 / 256, 256>>>(x);                             // 1
    k_metaprep<<<1, 1024>>>(adj);                                           // 2
    k_wprep<<<(512 * 128 + 255) / 256, 256>>>(gcnW, pWLh, pWLl, 512, 128);  // 3
    k_mixmma<<<2048, 256, DSM>>>(pXh, pXl, pYh, pYl);                       // 4 <- ncu
    k_mma<128, 0><<<dim3(1024, 2), 256, DSM>>>(pXh, pXl, pYh, pYl,
                                               pWLh, pWLl, nullptr, pZ,
                                               nullptr, nullptr, 8);

    // graph preprocessing
    k_init<<<256, 256>>>();
    k_hist<<<NEDGE / 256, 256>>>(sub + NEDGE);
    k_scan_partial<<<256, 256>>>();
    k_scan_block<<<1, 256>>>();
    k_scan_final<<<256, 256>>>();
    k_fill<<<NEDGE / 256, 256>>>(sub, sub + NEDGE);
    // remaining weight prep
    k_wprep<<<(512 * 128 + 255) / 256, 256>>>(gcnW + 65536, pWLh + 65536, pWLl + 65536, 512, 128);
    k_wprep<<<(512 * 128 + 255) / 256, 256>>>(gcnW + 131072, pWLh + 131072, pWLl + 131072, 512, 128);
    k_wprep<<<(128 * 128 + 255) / 256, 256>>>(W1, pW1h, pW1l, 128, 128);
    k_wprep<<<(128 * 64 + 255) / 256, 256>>>(W2, pW2h, pW2l, 128, 64);
    k_bsum<<<2, 256>>>(gcnB);

    // layer 0 aggregation (writes X pair for next layer)
    k_agg<<<NNODE / 8, 256>>>(pZ, pB, pXh, pXl);
    // layers 1..2
    for (int l = 1; l < NLAYER; l++) {
        k_mixmma<<<2048, 256, DSM>>>(pXh, pXl, pYh, pYl);
        k_mma<128, 0><<<dim3(1024, 2), 256, DSM>>>(pXh, pXl, pYh, pYl,
                                                   pWLh + (size_t)l * 65536,
                                                   pWLl + (size_t)l * 65536,
                                                   nullptr, pZ, nullptr, nullptr, 8);
        k_agg<<<NNODE / 8, 256>>>(pZ, pB + l * 128, pXh, pXl);
    }
    // MLP head: head1 -> Y0 pair (scratch), head2 -> out
    k_mma<128, 1><<<dim3(1024, 2), 256, DSM>>>(pXh, pXl, nullptr, nullptr,
                                               pW1h, pW1l, b1, nullptr, pYh, pYl, 2);
    k_mma<64, 2><<<dim3(1024, 1), 256, DSM>>>(pYh, pYl, nullptr, nullptr,
                                              pW2h, pW2l, b2, out, nullptr, nullptr, 2);
}

// round 16
// speedup vs baseline: 1.3227x; 1.0183x over previous
#include <cuda_runtime.h>
#include <cuda_bf16.h>
#include <cstdint>

#define NNODE 65536
#define NEDGE 1048576
#define NLAYER 3

// ---------------- scratch (static device globals) ---------------------------
__device__ float g_dinv[NNODE];
__device__ int   g_indeg[NNODE];
__device__ int   g_rowptr[NNODE + 1];
__device__ int   g_cursor[NNODE];
__device__ int   g_csr[NEDGE];
__device__ int   g_part[256];
__device__ float g_A[3][64 * 64];
__device__ __nv_bfloat16 g_Ahi[3 * 4096], g_Alo[3 * 4096];
__device__ float g_bsum[NLAYER][128];
__device__ float g_Z[(size_t)NNODE * 128];                       // raw H (fp32 for agg)
__device__ __nv_bfloat16 g_Yhi[(size_t)3 * NNODE * 128];
__device__ __nv_bfloat16 g_Ylo[(size_t)3 * NNODE * 128];
__device__ __nv_bfloat16 g_Xhi[(size_t)NNODE * 128];
__device__ __nv_bfloat16 g_Xlo[(size_t)NNODE * 128];
__device__ __nv_bfloat16 g_WLhi[3][128 * 512], g_WLlo[3][128 * 512];
__device__ __nv_bfloat16 g_W1hi[128 * 128],    g_W1lo[128 * 128];
__device__ __nv_bfloat16 g_W2hi[64 * 128],     g_W2lo[64 * 128];

// ================= helpers ====================================================
__device__ __forceinline__ uint32_t smem_to_u32(const void* p) {
    uint32_t a;
    asm("{ .reg .u64 t; cvta.to.shared.u64 t, %1; cvt.u32.u64 %0, t; }" : "=r"(a) : "l"(p));
    return a;
}
#define SMEM_SWIZZLE_128B(o) ((o) ^ (((o) >> 3) & 0x70))

#define LDSM_X4(r0, r1, r2, r3, addr) \
    asm volatile("ldmatrix.sync.aligned.m8n8.x4.shared.b16 {%0,%1,%2,%3}, [%4];" \
                 : "=r"(r0), "=r"(r1), "=r"(r2), "=r"(r3) : "r"(addr))
#define LDSM_X4_T(r0, r1, r2, r3, addr) \
    asm volatile("ldmatrix.sync.aligned.m8n8.x4.trans.shared.b16 {%0,%1,%2,%3}, [%4];" \
                 : "=r"(r0), "=r"(r1), "=r"(r2), "=r"(r3) : "r"(addr))

#define CP16(dst, src) \
    asm volatile("cp.async.cg.shared.global [%0], [%1], 16;" :: "r"(dst), "l"(src))
#define CP_COMMIT() asm volatile("cp.async.commit_group;" ::: "memory")
#define CP_WAIT1()  asm volatile("cp.async.wait_group 1;" ::: "memory")
#define CP_WAIT0()  asm volatile("cp.async.wait_group 0;" ::: "memory")

__device__ __forceinline__ void mma16816(float* c, const uint32_t* a, const uint32_t* b) {
    asm volatile(
        "mma.sync.aligned.m16n8k16.row.col.f32.bf16.bf16.f32 "
        "{%0,%1,%2,%3}, {%4,%5,%6,%7}, {%8,%9}, {%0,%1,%2,%3};"
        : "+f"(c[0]), "+f"(c[1]), "+f"(c[2]), "+f"(c[3])
        : "r"(a[0]), "r"(a[1]), "r"(a[2]), "r"(a[3]), "r"(b[0]), "r"(b[1]));
}

__device__ __forceinline__ void bf16split4(float4 v, uint2& hp, uint2& lp) {
    __nv_bfloat16 h0 = __float2bfloat16(v.x), h1 = __float2bfloat16(v.y);
    __nv_bfloat16 h2 = __float2bfloat16(v.z), h3 = __float2bfloat16(v.w);
    __nv_bfloat16 l0 = __float2bfloat16(v.x - __bfloat162float(h0));
    __nv_bfloat16 l1 = __float2bfloat16(v.y - __bfloat162float(h1));
    __nv_bfloat16 l2 = __float2bfloat16(v.z - __bfloat162float(h2));
    __nv_bfloat16 l3 = __float2bfloat16(v.w - __bfloat162float(h3));
    hp.x = (uint32_t)*(unsigned short*)&h0 | ((uint32_t)*(unsigned short*)&h1 << 16);
    hp.y = (uint32_t)*(unsigned short*)&h2 | ((uint32_t)*(unsigned short*)&h3 << 16);
    lp.x = (uint32_t)*(unsigned short*)&l0 | ((uint32_t)*(unsigned short*)&l1 << 16);
    lp.y = (uint32_t)*(unsigned short*)&l2 | ((uint32_t)*(unsigned short*)&l3 << 16);
}
__device__ __forceinline__ void bf16split2(float v0, float v1, uint32_t& hp, uint32_t& lp) {
    __nv_bfloat16 h0 = __float2bfloat16(v0), h1 = __float2bfloat16(v1);
    __nv_bfloat16 l0 = __float2bfloat16(v0 - __bfloat162float(h0));
    __nv_bfloat16 l1 = __float2bfloat16(v1 - __bfloat162float(h1));
    hp = (uint32_t)*(unsigned short*)&h0 | ((uint32_t)*(unsigned short*)&h1 << 16);
    lp = (uint32_t)*(unsigned short*)&l0 | ((uint32_t)*(unsigned short*)&l1 << 16);
}

// ---------------- graph preprocessing ---------------------------------------
__global__ void k_init() {
    int i = blockIdx.x * blockDim.x + threadIdx.x;
    if (i < NNODE) { g_indeg[i] = 0; g_cursor[i] = 0; }
}
__global__ void k_hist(const int* __restrict__ dst) {
    int e = blockIdx.x * blockDim.x + threadIdx.x;
    if (e < NEDGE) atomicAdd(&g_indeg[dst[e]], 1);
}
__global__ void k_scan_partial() {
    __shared__ int sh[256];
    int b = blockIdx.x, t = threadIdx.x;
    sh[t] = g_indeg[b * 256 + t];
    __syncthreads();
    for (int s = 128; s > 0; s >>= 1) {
        if (t < s) sh[t] += sh[t + s];
        __syncthreads();
    }
    if (t == 0) g_part[b] = sh[0];
}
__global__ void k_scan_block() {
    __shared__ int sh[256];
    int t = threadIdx.x;
    int v = g_part[t];
    sh[t] = v;
    __syncthreads();
    for (int off = 1; off < 256; off <<= 1) {
        int xv = (t >= off) ? sh[t - off] : 0;
        __syncthreads();
        sh[t] += xv;
        __syncthreads();
    }
    g_part[t] = sh[t] - v;
}
__global__ void k_scan_final() {
    __shared__ int sh[256];
    int b = blockIdx.x, t = threadIdx.x;
    int v = g_indeg[b * 256 + t];
    sh[t] = v;
    __syncthreads();
    for (int off = 1; off < 256; off <<= 1) {
        int xv = (t >= off) ? sh[t - off] : 0;
        __syncthreads();
        sh[t] += xv;
        __syncthreads();
    }
    int excl = sh[t] - v + g_part[b];
    g_rowptr[b * 256 + t] = excl;
    if (b == 255 && t == 255) g_rowptr[NNODE] = excl + v;
    g_dinv[b * 256 + t] = rsqrtf((float)(v + 1));
}
__global__ void k_fill(const int* __restrict__ src, const int* __restrict__ dst) {
    int e = blockIdx.x * blockDim.x + threadIdx.x;
    if (e < NEDGE) {
        int d = dst[e];
        int p = atomicAdd(&g_cursor[d], 1);
        g_csr[g_rowptr[d] + p] = src[e];
    }
}

// ---------------- fused meta prep --------------------------------------------
__global__ void __launch_bounds__(1024) k_metaprep(const float* __restrict__ adj) {
    float* Af = &g_A[0][0];
    int tid = threadIdx.x;
    for (int i = tid; i < 4096; i += 1024) Af[i] = adj[i];
    __syncthreads();
    {
        int c = tid & 63;
        for (int r = tid >> 6; r < 64; r += 16) {
            float s = 0.f;
#pragma unroll 16
            for (int k = 0; k < 64; k++) s += Af[r * 64 + k] * Af[k * 64 + c];
            Af[4096 + r * 64 + c] = s;
        }
    }
    __syncthreads();
    {
        int c = tid & 63;
        for (int r = tid >> 6; r < 64; r += 16) {
            float s = 0.f;
#pragma unroll 16
            for (int k = 0; k < 64; k++) s += Af[4096 + r * 64 + k] * Af[k * 64 + c];
            Af[8192 + r * 64 + c] = s;
        }
    }
    __syncthreads();
    for (int i = tid; i < 3 * 4096; i += 1024) {
        float v = Af[i];
        __nv_bfloat16 h = __float2bfloat16(v);
        g_Ahi[i] = h;
        g_Alo[i] = __float2bfloat16(v - __bfloat162float(h));
    }
}
__global__ void k_bsum(const float* __restrict__ gb) {
    int i = blockIdx.x * blockDim.x + threadIdx.x;
    if (i < NLAYER * 128) {
        int l = i / 128, c = i % 128;
        float s = 0.f;
        for (int j = 0; j < 4; j++) s += gb[(l * 4 + j) * 128 + c];
        g_bsum[l][c] = s;
    }
}

// weight prep: W[K x N] -> Wt_hi/lo[n][k]
__global__ void k_wprep(const float* __restrict__ W, __nv_bfloat16* __restrict__ hi,
                        __nv_bfloat16* __restrict__ lo, int K, int N) {
    int idx = blockIdx.x * 256 + threadIdx.x;
    if (idx >= K * N) return;
    int n = idx / K, k = idx % K;
    float v = W[(size_t)k * N + n];
    __nv_bfloat16 h = __float2bfloat16(v);
    hi[idx] = h;
    lo[idx] = __float2bfloat16(v - __bfloat162float(h));
}

// x fp32 -> Xhi/Xlo bf16 split (one-time, layer 0)
__global__ void k_xprep(const float* __restrict__ x) {
    int idx = blockIdx.x * 256 + threadIdx.x;
    float4 v = *((const float4*)x + idx);
    uint2 hp, lp;
    bf16split4(v, hp, lp);
    *((uint2*)g_Xhi + idx) = hp;
    *((uint2*)g_Xlo + idx) = lp;
}

// ---------------- HMMA mix (trans-B, cp.async X fill, no staging) -------------
// Y_i = A_i @ X, i=0..2. X tile stored NATURALLY [j][col] (64 rows x 128B,
// swizzled); B fragments read via ldmatrix.x4.trans. Dynamic smem 64 KB:
//   [Xh 8K][Xl 8K][Ah0..2 24K][Al0..2 24K]
__global__ void __launch_bounds__(256) k_mixmma(const __nv_bfloat16* __restrict__ Xh,
                                                const __nv_bfloat16* __restrict__ Xl,
                                                __nv_bfloat16* __restrict__ Yh,
                                                __nv_bfloat16* __restrict__ Yl) {
    extern __shared__ __align__(1024) unsigned char dynsm[];
    const uint32_t base = smem_to_u32(dynsm);
    const uint32_t xHiA = base, xLoA = base + 8192;
    const uint32_t aHi0 = base + 16384, aLo0 = base + 40960;
    int tid = threadIdx.x, lane = tid & 31, wid = tid >> 5;
    int wm = wid & 3, wn = wid >> 2;
    int col0 = blockIdx.x * 64;
    int g = lane >> 2, t4 = lane & 3;
    int aRow = lane & 15, aKb = (lane >> 4) * 16;
    // trans-B lane addressing on [j][col]: grp selects (k-half, n-half)
    int grp = lane >> 3;
    int tKr = (grp & 1) * 8 + (lane & 7);     // j-row within 16-row chunk
    int tNb = (grp >> 1) * 8;                 // col offset within 16

    // X tile fill: 64 rows x 128B (hi and lo) via cp.async — 4 CP16/thread
    {
        int r0 = tid >> 3,           u0 = tid & 7;           // idx = tid
        int r1 = (tid + 256) >> 3,   u1 = tid & 7;           // idx = tid + 256
        size_t s0 = (size_t)r0 * 131072 + col0 + u0 * 8;
        size_t s1 = (size_t)r1 * 131072 + col0 + u1 * 8;
        uint32_t d0 = SMEM_SWIZZLE_128B((uint32_t)(r0 * 128 + u0 * 16));
        uint32_t d1 = SMEM_SWIZZLE_128B((uint32_t)(r1 * 128 + u1 * 16));
        CP16(xHiA + d0, Xh + s0);
        CP16(xHiA + d1, Xh + s1);
        CP16(xLoA + d0, Xl + s0);
        CP16(xLoA + d1, Xl + s1);
        CP_COMMIT();
    }
    // A tiles: all 3 i, hi/lo (3072 uint2 units)
#pragma unroll
    for (int q = 0; q < 12; q++) {
        int idx = tid + 256 * q;
        int i = idx >> 10, rc = idx & 1023;
        int row = rc >> 4, k4 = (rc & 15) * 4;
        uint2 h = *(const uint2*)(g_Ahi + i * 4096 + row * 64 + k4);
        uint2 l = *(const uint2*)(g_Alo + i * 4096 + row * 64 + k4);
        uint32_t sw = SMEM_SWIZZLE_128B((uint32_t)(row * 128 + k4 * 2));
        *(uint2*)(dynsm + 16384 + i * 8192 + sw) = h;
        *(uint2*)(dynsm + 40960 + i * 8192 + sw) = l;
    }
    CP_WAIT0();
    __syncthreads();

    float acc[3][4][4] = {};
#pragma unroll
    for (int ks = 0; ks < 4; ks++) {
        // B (X^T) fragments: loaded once per ks via trans-ldmatrix
        uint32_t bh[4][2], bl[4][2];
#pragma unroll
        for (int np = 0; np < 2; np++) {
            int nb = wn * 32 + np * 16 + tNb;
            uint32_t bOff = SMEM_SWIZZLE_128B(
                (uint32_t)((ks * 16 + tKr) * 128 + nb * 2));
            LDSM_X4_T(bh[2 * np][0], bh[2 * np][1], bh[2 * np + 1][0], bh[2 * np + 1][1],
                      xHiA + bOff);
            LDSM_X4_T(bl[2 * np][0], bl[2 * np][1], bl[2 * np + 1][0], bl[2 * np + 1][1],
                      xLoA + bOff);
        }
        uint32_t aOff = SMEM_SWIZZLE_128B(
            (uint32_t)((wm * 16 + aRow) * 128 + ks * 32 + aKb));
#pragma unroll
        for (int i = 0; i < 3; i++) {
            uint32_t ah[4], al[4];
            LDSM_X4(ah[0], ah[1], ah[2], ah[3], aHi0 + i * 8192 + aOff);
            LDSM_X4(al[0], al[1], al[2], al[3], aLo0 + i * 8192 + aOff);
#pragma unroll
            for (int nt = 0; nt < 4; nt++) {
                mma16816(acc[i][nt], ah, bh[nt]);
                mma16816(acc[i][nt], al, bh[nt]);
                mma16816(acc[i][nt], ah, bl[nt]);
            }
        }
    }

#pragma unroll
    for (int i = 0; i < 3; i++) {
        __nv_bfloat16* Yhi = Yh + (size_t)i * NNODE * 128;
        __nv_bfloat16* Yli = Yl + (size_t)i * NNODE * 128;
#pragma unroll
        for (int half = 0; half < 2; half++) {
            int r = wm * 16 + g + half * 8;
            size_t rofs = (size_t)r * 131072;
#pragma unroll
            for (int nt = 0; nt < 4; nt++) {
                int col = col0 + wn * 32 + nt * 8 + t4 * 2;
                uint32_t hp, lp;
                bf16split2(acc[i][nt][half * 2 + 0], acc[i][nt][half * 2 + 1], hp, lp);
                *(uint32_t*)(Yhi + rofs + col) = hp;
                *(uint32_t*)(Yli + rofs + col) = lp;
            }
        }
    }
}

// ---------------- k_mma: cp.async double-buffered 64x64 GEMM ------------------
template <int NOUT, int MODE>
__global__ void __launch_bounds__(256) k_mma(
    const __nv_bfloat16* __restrict__ a0h, const __nv_bfloat16* __restrict__ a0l,
    const __nv_bfloat16* __restrict__ a1h, const __nv_bfloat16* __restrict__ a1l,
    const __nv_bfloat16* __restrict__ wtHi, const __nv_bfloat16* __restrict__ wtLo,
    const float* __restrict__ bias, float* __restrict__ C,
    __nv_bfloat16* __restrict__ Chi, __nv_bfloat16* __restrict__ Clo, int nChunks)
{
    extern __shared__ __align__(16) unsigned char dynsm[];
    const uint32_t base = smem_to_u32(dynsm);
    int tid = threadIdx.x, lane = tid & 31, wid = tid >> 5;
    int wm = wid & 3, wn = wid >> 2;
    int row0 = blockIdx.x * 64;
    int n0   = blockIdx.y * 64;
    int Ktot = nChunks * 64;
    int g = lane >> 2, t4 = lane & 3;
    int aRow = lane & 15;
    int aKb  = (lane >> 4) * 16;
    int bRow = ((lane >> 4) << 3) + (lane & 7);
    int bKb  = ((lane >> 3) & 1) * 16;
    int fr0 = tid >> 3, fu0 = tid & 7;
    int fr1 = (tid + 256) >> 3, fu1 = tid & 7;

    auto fill = [&](int stage, int c) {
        const __nv_bfloat16 *sh, *sl;
        int kk;
        if (c < 2) { sh = a0h; sl = a0l; kk = c * 64; }
        else {
            size_t off = (size_t)((c - 2) >> 1) * ((size_t)NNODE * 128);
            sh = a1h + off; sl = a1l + off; kk = (c & 1) * 64;
        }
        int kb = c * 64;
        uint32_t sb = base + stage * 32768;
        {
            size_t s0 = (size_t)(row0 + fr0) * 128 + kk + fu0 * 8;
            size_t s1 = (size_t)(row0 + fr1) * 128 + kk + fu1 * 8;
            uint32_t d0 = SMEM_SWIZZLE_128B((uint32_t)(fr0 * 128 + fu0 * 16));
            uint32_t d1 = SMEM_SWIZZLE_128B((uint32_t)(fr1 * 128 + fu1 * 16));
            CP16(sb + d0, sh + s0);
            CP16(sb + d1, sh + s1);
            CP16(sb + 8192 + d0, sl + s0);
            CP16(sb + 8192 + d1, sl + s1);
        }
        {
            size_t s0 = (size_t)(n0 + fr0) * Ktot + kb + fu0 * 8;
            size_t s1 = (size_t)(n0 + fr1) * Ktot + kb + fu1 * 8;
            uint32_t d0 = SMEM_SWIZZLE_128B((uint32_t)(fr0 * 128 + fu0 * 16));
            uint32_t d1 = SMEM_SWIZZLE_128B((uint32_t)(fr1 * 128 + fu1 * 16));
            CP16(sb + 16384 + d0, wtHi + s0);
            CP16(sb + 16384 + d1, wtHi + s1);
            CP16(sb + 24576 + d0, wtLo + s0);
            CP16(sb + 24576 + d1, wtLo + s1);
        }
        CP_COMMIT();
    };

    float acc[4][4] = {};
    fill(0, 0);
    for (int c = 0; c < nChunks; c++) {
        if (c + 1 < nChunks) { fill((c + 1) & 1, c + 1); CP_WAIT1(); }
        else                 { CP_WAIT0(); }
        __syncthreads();
        uint32_t sb = base + (c & 1) * 32768;
        uint32_t aHiA = sb, aLoA = sb + 8192, bHiA = sb + 16384, bLoA = sb + 24576;
#pragma unroll
        for (int ks = 0; ks < 4; ks++) {
            uint32_t ah[4], al[4];
            uint32_t aOff = SMEM_SWIZZLE_128B(
                (uint32_t)((wm * 16 + aRow) * 128 + ks * 32 + aKb));
            LDSM_X4(ah[0], ah[1], ah[2], ah[3], aHiA + aOff);
            LDSM_X4(al[0], al[1], al[2], al[3], aLoA + aOff);
            uint32_t bh[4][2], bl[4][2];
#pragma unroll
            for (int np = 0; np < 2; np++) {
                int nb = wn * 32 + np * 16;
                uint32_t bOff = SMEM_SWIZZLE_128B(
                    (uint32_t)((nb + bRow) * 128 + ks * 32 + bKb));
                LDSM_X4(bh[2 * np][0], bh[2 * np][1], bh[2 * np + 1][0], bh[2 * np + 1][1],
                        bHiA + bOff);
                LDSM_X4(bl[2 * np][0], bl[2 * np][1], bl[2 * np + 1][0], bl[2 * np + 1][1],
                        bLoA + bOff);
            }
#pragma unroll
            for (int nt = 0; nt < 4; nt++) {
                mma16816(acc[nt], ah, bh[nt]);
                mma16816(acc[nt], al, bh[nt]);
                mma16816(acc[nt], ah, bl[nt]);
            }
        }
        __syncthreads();
    }

#pragma unroll
    for (int half = 0; half < 2; half++) {
        int r = row0 + wm * 16 + g + half * 8;
#pragma unroll
        for (int nt = 0; nt < 4; nt++) {
            int col = n0 + wn * 32 + nt * 8 + t4 * 2;
            float v0 = acc[nt][half * 2 + 0];
            float v1 = acc[nt][half * 2 + 1];
            if (MODE >= 1) {
                v0 += bias[col]; v1 += bias[col + 1];
                if (MODE == 1) { v0 = fmaxf(v0, 0.f); v1 = fmaxf(v1, 0.f); }
            }
            if (MODE == 1) {
                uint32_t hp, lp;
                bf16split2(v0, v1, hp, lp);
                *(uint32_t*)(Chi + (size_t)r * NOUT + col) = hp;
                *(uint32_t*)(Clo + (size_t)r * NOUT + col) = lp;
            } else {
                *(float2*)(C + (size_t)r * NOUT + col) = make_float2(v0, v1);
            }
        }
    }
}

// ---------------- edge aggregation: fp32 in, bf16-pair out --------------------
__global__ void __launch_bounds__(256) k_agg(const float* __restrict__ H,
                                             const float* __restrict__ bsum,
                                             __nv_bfloat16* __restrict__ outH,
                                             __nv_bfloat16* __restrict__ outL) {
    int v = (blockIdx.x * 256 + threadIdx.x) >> 5;
    int lane = threadIdx.x & 31;
    if (v >= NNODE) return;
    float dv = g_dinv[v];
    float4 zv = *((const float4*)(H + (size_t)v * 128) + lane);
    float4 acc = make_float4(dv * zv.x, dv * zv.y, dv * zv.z, dv * zv.w);
    int p = g_rowptr[v], p1 = g_rowptr[v + 1];
    for (; p + 3 < p1; p += 4) {
        int u0 = g_csr[p], u1 = g_csr[p + 1], u2 = g_csr[p + 2], u3 = g_csr[p + 3];
        float d0 = g_dinv[u0], d1 = g_dinv[u1], d2 = g_dinv[u2], d3 = g_dinv[u3];
        float4 z0 = *((const float4*)(H + (size_t)u0 * 128) + lane);
        float4 z1 = *((const float4*)(H + (size_t)u1 * 128) + lane);
        float4 z2 = *((const float4*)(H + (size_t)u2 * 128) + lane);
        float4 z3 = *((const float4*)(H + (size_t)u3 * 128) + lane);
        acc.x += d0 * z0.x + d1 * z1.x + d2 * z2.x + d3 * z3.x;
        acc.y += d0 * z0.y + d1 * z1.y + d2 * z2.y + d3 * z3.y;
        acc.z += d0 * z0.z + d1 * z1.z + d2 * z2.z + d3 * z3.z;
        acc.w += d0 * z0.w + d1 * z1.w + d2 * z2.w + d3 * z3.w;
    }
    for (; p < p1; p++) {
        int u = g_csr[p];
        float du = g_dinv[u];
        float4 z = *((const float4*)(H + (size_t)u * 128) + lane);
        acc.x += du * z.x; acc.y += du * z.y;
        acc.z += du * z.z; acc.w += du * z.w;
    }
    float4 b = *((const float4*)bsum + lane);
    float4 o;
    o.x = fmaxf(dv * acc.x + b.x, 0.f);
    o.y = fmaxf(dv * acc.y + b.y, 0.f);
    o.z = fmaxf(dv * acc.z + b.z, 0.f);
    o.w = fmaxf(dv * acc.w + b.w, 0.f);
    uint2 hp, lp;
    bf16split4(o, hp, lp);
    *(uint2*)(outH + (size_t)v * 128 + lane * 4) = hp;
    *(uint2*)(outL + (size_t)v * 128 + lane * 4) = lp;
}

// ---------------- host orchestration -----------------------------------------
extern "C" void kernel_launch(void* const* d_in, const int* in_sizes, int n_in,
                              void* d_out, int out_size) {
    const float* x    = (const float*)d_in[0];
    const int*   sub  = (const int*)d_in[1];
    const float* adj  = (const float*)d_in[2];
    const float* gcnW = (const float*)d_in[3];
    const float* gcnB = (const float*)d_in[4];
    const float* W1   = (const float*)d_in[5];
    const float* b1   = (const float*)d_in[6];
    const float* W2   = (const float*)d_in[7];
    const float* b2   = (const float*)d_in[8];
    float* out = (float*)d_out;

    void* p;
    float *pZ, *pB;
    __nv_bfloat16 *pYh, *pYl, *pXh, *pXl;
    __nv_bfloat16 *pWLh, *pWLl, *pW1h, *pW1l, *pW2h, *pW2l;
    cudaGetSymbolAddress(&p, g_Z);    pZ  = (float*)p;
    cudaGetSymbolAddress(&p, g_bsum); pB  = (float*)p;
    cudaGetSymbolAddress(&p, g_Yhi);  pYh = (__nv_bfloat16*)p;
    cudaGetSymbolAddress(&p, g_Ylo);  pYl = (__nv_bfloat16*)p;
    cudaGetSymbolAddress(&p, g_Xhi);  pXh = (__nv_bfloat16*)p;
    cudaGetSymbolAddress(&p, g_Xlo);  pXl = (__nv_bfloat16*)p;
    cudaGetSymbolAddress(&p, g_WLhi); pWLh = (__nv_bfloat16*)p;
    cudaGetSymbolAddress(&p, g_WLlo); pWLl = (__nv_bfloat16*)p;
    cudaGetSymbolAddress(&p, g_W1hi); pW1h = (__nv_bfloat16*)p;
    cudaGetSymbolAddress(&p, g_W1lo); pW1l = (__nv_bfloat16*)p;
    cudaGetSymbolAddress(&p, g_W2hi); pW2h = (__nv_bfloat16*)p;
    cudaGetSymbolAddress(&p, g_W2lo); pW2l = (__nv_bfloat16*)p;

    const int DSM = 65536;
    cudaFuncSetAttribute(k_mma<128, 0>, cudaFuncAttributeMaxDynamicSharedMemorySize, DSM);
    cudaFuncSetAttribute(k_mma<128, 1>, cudaFuncAttributeMaxDynamicSharedMemorySize, DSM);
    cudaFuncSetAttribute(k_mma<64, 2>,  cudaFuncAttributeMaxDynamicSharedMemorySize, DSM);
    cudaFuncSetAttribute(k_mixmma,      cudaFuncAttributeMaxDynamicSharedMemorySize, DSM);

    // deps of first k_mma; slot 4 = k_mixmma (profiled)
    k_xprep<<<NNODE * 128 / 4 / 256, 256>>>(x);                             // 1
    k_metaprep<<<1, 1024>>>(adj);                                           // 2
    k_wprep<<<(512 * 128 + 255) / 256, 256>>>(gcnW, pWLh, pWLl, 512, 128);  // 3
    k_mixmma<<<2048, 256, DSM>>>(pXh, pXl, pYh, pYl);                       // 4 <- ncu
    k_mma<128, 0><<<dim3(1024, 2), 256, DSM>>>(pXh, pXl, pYh, pYl,
                                               pWLh, pWLl, nullptr, pZ,
                                               nullptr, nullptr, 8);

    // graph preprocessing
    k_init<<<256, 256>>>();
    k_hist<<<NEDGE / 256, 256>>>(sub + NEDGE);
    k_scan_partial<<<256, 256>>>();
    k_scan_block<<<1, 256>>>();
    k_scan_final<<<256, 256>>>();
    k_fill<<<NEDGE / 256, 256>>>(sub, sub + NEDGE);
    // remaining weight prep
    k_wprep<<<(512 * 128 + 255) / 256, 256>>>(gcnW + 65536, pWLh + 65536, pWLl + 65536, 512, 128);
    k_wprep<<<(512 * 128 + 255) / 256, 256>>>(gcnW + 131072, pWLh + 131072, pWLl + 131072, 512, 128);
    k_wprep<<<(128 * 128 + 255) / 256, 256>>>(W1, pW1h, pW1l, 128, 128);
    k_wprep<<<(128 * 64 + 255) / 256, 256>>>(W2, pW2h, pW2l, 128, 64);
    k_bsum<<<2, 256>>>(gcnB);

    // layer 0 aggregation (writes X pair for next layer)
    k_agg<<<NNODE / 8, 256>>>(pZ, pB, pXh, pXl);
    // layers 1..2
    for (int l = 1; l < NLAYER; l++) {
        k_mixmma<<<2048, 256, DSM>>>(pXh, pXl, pYh, pYl);
        k_mma<128, 0><<<dim3(1024, 2), 256, DSM>>>(pXh, pXl, pYh, pYl,
                                                   pWLh + (size_t)l * 65536,
                                                   pWLl + (size_t)l * 65536,
                                                   nullptr, pZ, nullptr, nullptr, 8);
        k_agg<<<NNODE / 8, 256>>>(pZ, pB + l * 128, pXh, pXl);
    }
    // MLP head: head1 -> Y0 pair (scratch), head2 -> out
    k_mma<128, 1><<<dim3(1024, 2), 256, DSM>>>(pXh, pXl, nullptr, nullptr,
                                               pW1h, pW1l, b1, nullptr, pYh, pYl, 2);
    k_mma<64, 2><<<dim3(1024, 1), 256, DSM>>>(pYh, pYl, nullptr, nullptr,
                                              pW2h, pW2l, b2, out, nullptr, nullptr, 2);
}

// round 17
// speedup vs baseline: 1.3501x; 1.0208x over previous
#include <cuda_runtime.h>
#include <cuda_bf16.h>
#include <cstdint>

#define NNODE 65536
#define NEDGE 1048576
#define NLAYER 3

// ---------------- scratch (static device globals) ---------------------------
__device__ float g_dinv[NNODE];
__device__ int   g_indeg[NNODE];
__device__ int   g_rowptr[NNODE + 1];
__device__ int   g_cursor[NNODE];
__device__ int   g_csr[NEDGE];
__device__ int   g_part[256];
__device__ float g_A[3][64 * 64];
__device__ __nv_bfloat16 g_Ahi[3 * 4096], g_Alo[3 * 4096];
__device__ float g_bsum[NLAYER][128];
__device__ float g_Z[(size_t)NNODE * 128];                       // raw H (fp32 for agg)
__device__ __nv_bfloat16 g_Yhi[(size_t)3 * NNODE * 128];
__device__ __nv_bfloat16 g_Ylo[(size_t)3 * NNODE * 128];
__device__ __nv_bfloat16 g_Xhi[(size_t)NNODE * 128];
__device__ __nv_bfloat16 g_Xlo[(size_t)NNODE * 128];
__device__ __nv_bfloat16 g_WLhi[3][128 * 512], g_WLlo[3][128 * 512];
__device__ __nv_bfloat16 g_W1hi[128 * 128],    g_W1lo[128 * 128];
__device__ __nv_bfloat16 g_W2hi[64 * 128],     g_W2lo[64 * 128];

// ================= helpers ====================================================
__device__ __forceinline__ uint32_t smem_to_u32(const void* p) {
    uint32_t a;
    asm("{ .reg .u64 t; cvta.to.shared.u64 t, %1; cvt.u32.u64 %0, t; }" : "=r"(a) : "l"(p));
    return a;
}
#define SMEM_SWIZZLE_128B(o) ((o) ^ (((o) >> 3) & 0x70))

#define LDSM_X4(r0, r1, r2, r3, addr) \
    asm volatile("ldmatrix.sync.aligned.m8n8.x4.shared.b16 {%0,%1,%2,%3}, [%4];" \
                 : "=r"(r0), "=r"(r1), "=r"(r2), "=r"(r3) : "r"(addr))
#define LDSM_X4_T(r0, r1, r2, r3, addr) \
    asm volatile("ldmatrix.sync.aligned.m8n8.x4.trans.shared.b16 {%0,%1,%2,%3}, [%4];" \
                 : "=r"(r0), "=r"(r1), "=r"(r2), "=r"(r3) : "r"(addr))

#define CP16(dst, src) \
    asm volatile("cp.async.cg.shared.global [%0], [%1], 16;" :: "r"(dst), "l"(src))
#define CP_COMMIT() asm volatile("cp.async.commit_group;" ::: "memory")
#define CP_WAIT1()  asm volatile("cp.async.wait_group 1;" ::: "memory")
#define CP_WAIT0()  asm volatile("cp.async.wait_group 0;" ::: "memory")

__device__ __forceinline__ void mma16816(float* c, const uint32_t* a, const uint32_t* b) {
    asm volatile(
        "mma.sync.aligned.m16n8k16.row.col.f32.bf16.bf16.f32 "
        "{%0,%1,%2,%3}, {%4,%5,%6,%7}, {%8,%9}, {%0,%1,%2,%3};"
        : "+f"(c[0]), "+f"(c[1]), "+f"(c[2]), "+f"(c[3])
        : "r"(a[0]), "r"(a[1]), "r"(a[2]), "r"(a[3]), "r"(b[0]), "r"(b[1]));
}

__device__ __forceinline__ void bf16split4(float4 v, uint2& hp, uint2& lp) {
    __nv_bfloat16 h0 = __float2bfloat16(v.x), h1 = __float2bfloat16(v.y);
    __nv_bfloat16 h2 = __float2bfloat16(v.z), h3 = __float2bfloat16(v.w);
    __nv_bfloat16 l0 = __float2bfloat16(v.x - __bfloat162float(h0));
    __nv_bfloat16 l1 = __float2bfloat16(v.y - __bfloat162float(h1));
    __nv_bfloat16 l2 = __float2bfloat16(v.z - __bfloat162float(h2));
    __nv_bfloat16 l3 = __float2bfloat16(v.w - __bfloat162float(h3));
    hp.x = (uint32_t)*(unsigned short*)&h0 | ((uint32_t)*(unsigned short*)&h1 << 16);
    hp.y = (uint32_t)*(unsigned short*)&h2 | ((uint32_t)*(unsigned short*)&h3 << 16);
    lp.x = (uint32_t)*(unsigned short*)&l0 | ((uint32_t)*(unsigned short*)&l1 << 16);
    lp.y = (uint32_t)*(unsigned short*)&l2 | ((uint32_t)*(unsigned short*)&l3 << 16);
}
__device__ __forceinline__ void bf16split2(float v0, float v1, uint32_t& hp, uint32_t& lp) {
    __nv_bfloat16 h0 = __float2bfloat16(v0), h1 = __float2bfloat16(v1);
    __nv_bfloat16 l0 = __float2bfloat16(v0 - __bfloat162float(h0));
    __nv_bfloat16 l1 = __float2bfloat16(v1 - __bfloat162float(h1));
    hp = (uint32_t)*(unsigned short*)&h0 | ((uint32_t)*(unsigned short*)&h1 << 16);
    lp = (uint32_t)*(unsigned short*)&l0 | ((uint32_t)*(unsigned short*)&l1 << 16);
}

// ---------------- graph preprocessing ---------------------------------------
__global__ void k_init() {
    int i = blockIdx.x * blockDim.x + threadIdx.x;
    if (i < NNODE) { g_indeg[i] = 0; g_cursor[i] = 0; }
}
__global__ void k_hist(const int* __restrict__ dst) {
    int e = blockIdx.x * blockDim.x + threadIdx.x;
    if (e < NEDGE) atomicAdd(&g_indeg[dst[e]], 1);
}
__global__ void k_scan_partial() {
    __shared__ int sh[256];
    int b = blockIdx.x, t = threadIdx.x;
    sh[t] = g_indeg[b * 256 + t];
    __syncthreads();
    for (int s = 128; s > 0; s >>= 1) {
        if (t < s) sh[t] += sh[t + s];
        __syncthreads();
    }
    if (t == 0) g_part[b] = sh[0];
}
__global__ void k_scan_block() {
    __shared__ int sh[256];
    int t = threadIdx.x;
    int v = g_part[t];
    sh[t] = v;
    __syncthreads();
    for (int off = 1; off < 256; off <<= 1) {
        int xv = (t >= off) ? sh[t - off] : 0;
        __syncthreads();
        sh[t] += xv;
        __syncthreads();
    }
    g_part[t] = sh[t] - v;
}
__global__ void k_scan_final() {
    __shared__ int sh[256];
    int b = blockIdx.x, t = threadIdx.x;
    int v = g_indeg[b * 256 + t];
    sh[t] = v;
    __syncthreads();
    for (int off = 1; off < 256; off <<= 1) {
        int xv = (t >= off) ? sh[t - off] : 0;
        __syncthreads();
        sh[t] += xv;
        __syncthreads();
    }
    int excl = sh[t] - v + g_part[b];
    g_rowptr[b * 256 + t] = excl;
    if (b == 255 && t == 255) g_rowptr[NNODE] = excl + v;
    g_dinv[b * 256 + t] = rsqrtf((float)(v + 1));
}
__global__ void k_fill(const int* __restrict__ src, const int* __restrict__ dst) {
    int e = blockIdx.x * blockDim.x + threadIdx.x;
    if (e < NEDGE) {
        int d = dst[e];
        int p = atomicAdd(&g_cursor[d], 1);
        g_csr[g_rowptr[d] + p] = src[e];
    }
}

// ---------------- fused meta prep --------------------------------------------
__global__ void __launch_bounds__(1024) k_metaprep(const float* __restrict__ adj) {
    float* Af = &g_A[0][0];
    int tid = threadIdx.x;
    for (int i = tid; i < 4096; i += 1024) Af[i] = adj[i];
    __syncthreads();
    {
        int c = tid & 63;
        for (int r = tid >> 6; r < 64; r += 16) {
            float s = 0.f;
#pragma unroll 16
            for (int k = 0; k < 64; k++) s += Af[r * 64 + k] * Af[k * 64 + c];
            Af[4096 + r * 64 + c] = s;
        }
    }
    __syncthreads();
    {
        int c = tid & 63;
        for (int r = tid >> 6; r < 64; r += 16) {
            float s = 0.f;
#pragma unroll 16
            for (int k = 0; k < 64; k++) s += Af[4096 + r * 64 + k] * Af[k * 64 + c];
            Af[8192 + r * 64 + c] = s;
        }
    }
    __syncthreads();
    for (int i = tid; i < 3 * 4096; i += 1024) {
        float v = Af[i];
        __nv_bfloat16 h = __float2bfloat16(v);
        g_Ahi[i] = h;
        g_Alo[i] = __float2bfloat16(v - __bfloat162float(h));
    }
}
__global__ void k_bsum(const float* __restrict__ gb) {
    int i = blockIdx.x * blockDim.x + threadIdx.x;
    if (i < NLAYER * 128) {
        int l = i / 128, c = i % 128;
        float s = 0.f;
        for (int j = 0; j < 4; j++) s += gb[(l * 4 + j) * 128 + c];
        g_bsum[l][c] = s;
    }
}

// weight prep: W[K x N] -> Wt_hi/lo[n][k]
__global__ void k_wprep(const float* __restrict__ W, __nv_bfloat16* __restrict__ hi,
                        __nv_bfloat16* __restrict__ lo, int K, int N) {
    int idx = blockIdx.x * 256 + threadIdx.x;
    if (idx >= K * N) return;
    int n = idx / K, k = idx % K;
    float v = W[(size_t)k * N + n];
    __nv_bfloat16 h = __float2bfloat16(v);
    hi[idx] = h;
    lo[idx] = __float2bfloat16(v - __bfloat162float(h));
}

// fused: x split (blocks 0..8191) + layer-0 weight split (blocks 8192..8447)
__global__ void k_prep0(const float* __restrict__ x, const float* __restrict__ gcnW) {
    int b = blockIdx.x;
    if (b < 8192) {
        int idx = b * 256 + threadIdx.x;               // 2M float4 units
        float4 v = *((const float4*)x + idx);
        uint2 hp, lp;
        bf16split4(v, hp, lp);
        *((uint2*)g_Xhi + idx) = hp;
        *((uint2*)g_Xlo + idx) = lp;
    } else {
        int idx = (b - 8192) * 256 + threadIdx.x;      // 65536 weight elems
        int n = idx / 512, k = idx % 512;
        float v = gcnW[(size_t)k * 128 + n];
        __nv_bfloat16 h = __float2bfloat16(v);
        g_WLhi[0][idx] = h;
        g_WLlo[0][idx] = __float2bfloat16(v - __bfloat162float(h));
    }
}

// ---------------- HMMA mix (trans-B, cp.async X fill) -------------------------
__global__ void __launch_bounds__(256) k_mixmma(const __nv_bfloat16* __restrict__ Xh,
                                                const __nv_bfloat16* __restrict__ Xl,
                                                __nv_bfloat16* __restrict__ Yh,
                                                __nv_bfloat16* __restrict__ Yl) {
    extern __shared__ __align__(1024) unsigned char dynsm[];
    const uint32_t base = smem_to_u32(dynsm);
    const uint32_t xHiA = base, xLoA = base + 8192;
    const uint32_t aHi0 = base + 16384, aLo0 = base + 40960;
    int tid = threadIdx.x, lane = tid & 31, wid = tid >> 5;
    int wm = wid & 3, wn = wid >> 2;
    int col0 = blockIdx.x * 64;
    int g = lane >> 2, t4 = lane & 3;
    int aRow = lane & 15, aKb = (lane >> 4) * 16;
    int grp = lane >> 3;
    int tKr = (grp & 1) * 8 + (lane & 7);
    int tNb = (grp >> 1) * 8;

    {
        int r0 = tid >> 3,           u0 = tid & 7;
        int r1 = (tid + 256) >> 3,   u1 = tid & 7;
        size_t s0 = (size_t)r0 * 131072 + col0 + u0 * 8;
        size_t s1 = (size_t)r1 * 131072 + col0 + u1 * 8;
        uint32_t d0 = SMEM_SWIZZLE_128B((uint32_t)(r0 * 128 + u0 * 16));
        uint32_t d1 = SMEM_SWIZZLE_128B((uint32_t)(r1 * 128 + u1 * 16));
        CP16(xHiA + d0, Xh + s0);
        CP16(xHiA + d1, Xh + s1);
        CP16(xLoA + d0, Xl + s0);
        CP16(xLoA + d1, Xl + s1);
        CP_COMMIT();
    }
#pragma unroll
    for (int q = 0; q < 12; q++) {
        int idx = tid + 256 * q;
        int i = idx >> 10, rc = idx & 1023;
        int row = rc >> 4, k4 = (rc & 15) * 4;
        uint2 h = *(const uint2*)(g_Ahi + i * 4096 + row * 64 + k4);
        uint2 l = *(const uint2*)(g_Alo + i * 4096 + row * 64 + k4);
        uint32_t sw = SMEM_SWIZZLE_128B((uint32_t)(row * 128 + k4 * 2));
        *(uint2*)(dynsm + 16384 + i * 8192 + sw) = h;
        *(uint2*)(dynsm + 40960 + i * 8192 + sw) = l;
    }
    CP_WAIT0();
    __syncthreads();

    float acc[3][4][4] = {};
#pragma unroll
    for (int ks = 0; ks < 4; ks++) {
        uint32_t bh[4][2], bl[4][2];
#pragma unroll
        for (int np = 0; np < 2; np++) {
            int nb = wn * 32 + np * 16 + tNb;
            uint32_t bOff = SMEM_SWIZZLE_128B(
                (uint32_t)((ks * 16 + tKr) * 128 + nb * 2));
            LDSM_X4_T(bh[2 * np][0], bh[2 * np][1], bh[2 * np + 1][0], bh[2 * np + 1][1],
                      xHiA + bOff);
            LDSM_X4_T(bl[2 * np][0], bl[2 * np][1], bl[2 * np + 1][0], bl[2 * np + 1][1],
                      xLoA + bOff);
        }
        uint32_t aOff = SMEM_SWIZZLE_128B(
            (uint32_t)((wm * 16 + aRow) * 128 + ks * 32 + aKb));
#pragma unroll
        for (int i = 0; i < 3; i++) {
            uint32_t ah[4], al[4];
            LDSM_X4(ah[0], ah[1], ah[2], ah[3], aHi0 + i * 8192 + aOff);
            LDSM_X4(al[0], al[1], al[2], al[3], aLo0 + i * 8192 + aOff);
#pragma unroll
            for (int nt = 0; nt < 4; nt++) {
                mma16816(acc[i][nt], ah, bh[nt]);
                mma16816(acc[i][nt], al, bh[nt]);
                mma16816(acc[i][nt], ah, bl[nt]);
            }
        }
    }

#pragma unroll
    for (int i = 0; i < 3; i++) {
        __nv_bfloat16* Yhi = Yh + (size_t)i * NNODE * 128;
        __nv_bfloat16* Yli = Yl + (size_t)i * NNODE * 128;
#pragma unroll
        for (int half = 0; half < 2; half++) {
            int r = wm * 16 + g + half * 8;
            size_t rofs = (size_t)r * 131072;
#pragma unroll
            for (int nt = 0; nt < 4; nt++) {
                int col = col0 + wn * 32 + nt * 8 + t4 * 2;
                uint32_t hp, lp;
                bf16split2(acc[i][nt][half * 2 + 0], acc[i][nt][half * 2 + 1], hp, lp);
                *(uint32_t*)(Yhi + rofs + col) = hp;
                *(uint32_t*)(Yli + rofs + col) = lp;
            }
        }
    }
}

// ---------------- k_mma: cp.async double-buffered 64xNOUT GEMM ----------------
// One CTA covers ALL NOUT output cols (A smem reused, not re-read per n-block).
// stage = [Ah 8K][Al 8K][Bh NOUT*128][Bl NOUT*128]; 2 stages.
// MODE 0: fp32 C (raw H). MODE 1: relu(+bias) -> Chi/Clo pair. MODE 2: +bias -> fp32 C.
template <int NOUT, int MODE>
__global__ void __launch_bounds__(256) k_mma(
    const __nv_bfloat16* __restrict__ a0h, const __nv_bfloat16* __restrict__ a0l,
    const __nv_bfloat16* __restrict__ a1h, const __nv_bfloat16* __restrict__ a1l,
    const __nv_bfloat16* __restrict__ wtHi, const __nv_bfloat16* __restrict__ wtLo,
    const float* __restrict__ bias, float* __restrict__ C,
    __nv_bfloat16* __restrict__ Chi, __nv_bfloat16* __restrict__ Clo, int nChunks)
{
    constexpr int BB = NOUT * 128;          // bytes per B array per stage
    constexpr int STAGE = 16384 + 2 * BB;
    constexpr int NT = NOUT / 16;           // n8-tile pairs per warp... acc tiles
    extern __shared__ __align__(16) unsigned char dynsm[];
    const uint32_t base = smem_to_u32(dynsm);
    int tid = threadIdx.x, lane = tid & 31, wid = tid >> 5;
    int wm = wid & 3, wn = wid >> 2;
    int row0 = blockIdx.x * 64;
    int Ktot = nChunks * 64;
    int g = lane >> 2, t4 = lane & 3;
    int aRow = lane & 15;
    int aKb  = (lane >> 4) * 16;
    int bRow = ((lane >> 4) << 3) + (lane & 7);
    int bKb  = ((lane >> 3) & 1) * 16;

    auto fill = [&](int stage, int c) {
        const __nv_bfloat16 *sh, *sl;
        int kk;
        if (c < 2) { sh = a0h; sl = a0l; kk = c * 64; }
        else {
            size_t off = (size_t)((c - 2) >> 1) * ((size_t)NNODE * 128);
            sh = a1h + off; sl = a1l + off; kk = (c & 1) * 64;
        }
        int kb = c * 64;
        uint32_t sb = base + stage * STAGE;
        // A hi/lo: 64 rows x 8 units (512 units each)
#pragma unroll
        for (int q = 0; q < 2; q++) {
            int idx = tid + 256 * q;
            int r = idx >> 3, u = idx & 7;
            size_t s = (size_t)(row0 + r) * 128 + kk + u * 8;
            uint32_t d = SMEM_SWIZZLE_128B((uint32_t)(r * 128 + u * 16));
            CP16(sb + d, sh + s);
            CP16(sb + 8192 + d, sl + s);
        }
        // B hi/lo: NOUT rows x 8 units
#pragma unroll
        for (int q = 0; q < NOUT / 32; q++) {
            int idx = tid + 256 * q;
            int r = idx >> 3, u = idx & 7;
            size_t s = (size_t)r * Ktot + kb + u * 8;
            uint32_t d = SMEM_SWIZZLE_128B((uint32_t)(r * 128 + u * 16));
            CP16(sb + 16384 + d, wtHi + s);
            CP16(sb + 16384 + BB + d, wtLo + s);
        }
        CP_COMMIT();
    };

    float acc[NT][4] = {};
    fill(0, 0);
    for (int c = 0; c < nChunks; c++) {
        if (c + 1 < nChunks) { fill((c + 1) & 1, c + 1); CP_WAIT1(); }
        else                 { CP_WAIT0(); }
        __syncthreads();
        uint32_t sb = base + (c & 1) * STAGE;
        uint32_t aHiA = sb, aLoA = sb + 8192, bHiA = sb + 16384, bLoA = sb + 16384 + BB;
#pragma unroll
        for (int ks = 0; ks < 4; ks++) {
            uint32_t ah[4], al[4];
            uint32_t aOff = SMEM_SWIZZLE_128B(
                (uint32_t)((wm * 16 + aRow) * 128 + ks * 32 + aKb));
            LDSM_X4(ah[0], ah[1], ah[2], ah[3], aHiA + aOff);
            LDSM_X4(al[0], al[1], al[2], al[3], aLoA + aOff);
#pragma unroll
            for (int np = 0; np < NOUT / 32; np++) {
                int nb = wn * (NOUT / 2) + np * 16;
                uint32_t bOff = SMEM_SWIZZLE_128B(
                    (uint32_t)((nb + bRow) * 128 + ks * 32 + bKb));
                uint32_t bh[2][2], bl[2][2];
                LDSM_X4(bh[0][0], bh[0][1], bh[1][0], bh[1][1], bHiA + bOff);
                LDSM_X4(bl[0][0], bl[0][1], bl[1][0], bl[1][1], bLoA + bOff);
#pragma unroll
                for (int t = 0; t < 2; t++) {
                    int nt = np * 2 + t;
                    mma16816(acc[nt], ah, bh[t]);
                    mma16816(acc[nt], al, bh[t]);
                    mma16816(acc[nt], ah, bl[t]);
                }
            }
        }
        __syncthreads();
    }

#pragma unroll
    for (int half = 0; half < 2; half++) {
        int r = row0 + wm * 16 + g + half * 8;
#pragma unroll
        for (int nt = 0; nt < NT; nt++) {
            int col = wn * (NOUT / 2) + nt * 8 + t4 * 2;
            float v0 = acc[nt][half * 2 + 0];
            float v1 = acc[nt][half * 2 + 1];
            if (MODE >= 1) {
                v0 += bias[col]; v1 += bias[col + 1];
                if (MODE == 1) { v0 = fmaxf(v0, 0.f); v1 = fmaxf(v1, 0.f); }
            }
            if (MODE == 1) {
                uint32_t hp, lp;
                bf16split2(v0, v1, hp, lp);
                *(uint32_t*)(Chi + (size_t)r * NOUT + col) = hp;
                *(uint32_t*)(Clo + (size_t)r * NOUT + col) = lp;
            } else {
                *(float2*)(C + (size_t)r * NOUT + col) = make_float2(v0, v1);
            }
        }
    }
}

// ---------------- edge aggregation: fp32 in, bf16-pair out --------------------
__global__ void __launch_bounds__(256) k_agg(const float* __restrict__ H,
                                             const float* __restrict__ bsum,
                                             __nv_bfloat16* __restrict__ outH,
                                             __nv_bfloat16* __restrict__ outL) {
    int v = (blockIdx.x * 256 + threadIdx.x) >> 5;
    int lane = threadIdx.x & 31;
    if (v >= NNODE) return;
    float dv = g_dinv[v];
    float4 zv = *((const float4*)(H + (size_t)v * 128) + lane);
    float4 acc = make_float4(dv * zv.x, dv * zv.y, dv * zv.z, dv * zv.w);
    int p = g_rowptr[v], p1 = g_rowptr[v + 1];
    for (; p + 3 < p1; p += 4) {
        int u0 = g_csr[p], u1 = g_csr[p + 1], u2 = g_csr[p + 2], u3 = g_csr[p + 3];
        float d0 = g_dinv[u0], d1 = g_dinv[u1], d2 = g_dinv[u2], d3 = g_dinv[u3];
        float4 z0 = *((const float4*)(H + (size_t)u0 * 128) + lane);
        float4 z1 = *((const float4*)(H + (size_t)u1 * 128) + lane);
        float4 z2 = *((const float4*)(H + (size_t)u2 * 128) + lane);
        float4 z3 = *((const float4*)(H + (size_t)u3 * 128) + lane);
        acc.x += d0 * z0.x + d1 * z1.x + d2 * z2.x + d3 * z3.x;
        acc.y += d0 * z0.y + d1 * z1.y + d2 * z2.y + d3 * z3.y;
        acc.z += d0 * z0.z + d1 * z1.z + d2 * z2.z + d3 * z3.z;
        acc.w += d0 * z0.w + d1 * z1.w + d2 * z2.w + d3 * z3.w;
    }
    for (; p < p1; p++) {
        int u = g_csr[p];
        float du = g_dinv[u];
        float4 z = *((const float4*)(H + (size_t)u * 128) + lane);
        acc.x += du * z.x; acc.y += du * z.y;
        acc.z += du * z.z; acc.w += du * z.w;
    }
    float4 b = *((const float4*)bsum + lane);
    float4 o;
    o.x = fmaxf(dv * acc.x + b.x, 0.f);
    o.y = fmaxf(dv * acc.y + b.y, 0.f);
    o.z = fmaxf(dv * acc.z + b.z, 0.f);
    o.w = fmaxf(dv * acc.w + b.w, 0.f);
    uint2 hp, lp;
    bf16split4(o, hp, lp);
    *(uint2*)(outH + (size_t)v * 128 + lane * 4) = hp;
    *(uint2*)(outL + (size_t)v * 128 + lane * 4) = lp;
}

// ---------------- host orchestration -----------------------------------------
extern "C" void kernel_launch(void* const* d_in, const int* in_sizes, int n_in,
                              void* d_out, int out_size) {
    const float* x    = (const float*)d_in[0];
    const int*   sub  = (const int*)d_in[1];
    const float* adj  = (const float*)d_in[2];
    const float* gcnW = (const float*)d_in[3];
    const float* gcnB = (const float*)d_in[4];
    const float* W1   = (const float*)d_in[5];
    const float* b1   = (const float*)d_in[6];
    const float* W2   = (const float*)d_in[7];
    const float* b2   = (const float*)d_in[8];
    float* out = (float*)d_out;

    void* p;
    float *pZ, *pB;
    __nv_bfloat16 *pYh, *pYl, *pXh, *pXl;
    __nv_bfloat16 *pWLh, *pWLl, *pW1h, *pW1l, *pW2h, *pW2l;
    cudaGetSymbolAddress(&p, g_Z);    pZ  = (float*)p;
    cudaGetSymbolAddress(&p, g_bsum); pB  = (float*)p;
    cudaGetSymbolAddress(&p, g_Yhi);  pYh = (__nv_bfloat16*)p;
    cudaGetSymbolAddress(&p, g_Ylo);  pYl = (__nv_bfloat16*)p;
    cudaGetSymbolAddress(&p, g_Xhi);  pXh = (__nv_bfloat16*)p;
    cudaGetSymbolAddress(&p, g_Xlo);  pXl = (__nv_bfloat16*)p;
    cudaGetSymbolAddress(&p, g_WLhi); pWLh = (__nv_bfloat16*)p;
    cudaGetSymbolAddress(&p, g_WLlo); pWLl = (__nv_bfloat16*)p;
    cudaGetSymbolAddress(&p, g_W1hi); pW1h = (__nv_bfloat16*)p;
    cudaGetSymbolAddress(&p, g_W1lo); pW1l = (__nv_bfloat16*)p;
    cudaGetSymbolAddress(&p, g_W2hi); pW2h = (__nv_bfloat16*)p;
    cudaGetSymbolAddress(&p, g_W2lo); pW2l = (__nv_bfloat16*)p;

    const int DSM128 = 2 * (16384 + 2 * 128 * 128);   // 98304
    const int DSM64  = 2 * (16384 + 2 * 64 * 128);    // 65536
    const int DSMMIX = 65536;
    cudaFuncSetAttribute(k_mma<128, 0>, cudaFuncAttributeMaxDynamicSharedMemorySize, DSM128);
    cudaFuncSetAttribute(k_mma<128, 1>, cudaFuncAttributeMaxDynamicSharedMemorySize, DSM128);
    cudaFuncSetAttribute(k_mma<64, 2>,  cudaFuncAttributeMaxDynamicSharedMemorySize, DSM64);
    cudaFuncSetAttribute(k_mixmma,      cudaFuncAttributeMaxDynamicSharedMemorySize, DSMMIX);

    // deps of first k_mma; slot 4 = k_mma (profiled)
    k_prep0<<<8448, 256>>>(x, gcnW);                                        // 1
    k_metaprep<<<1, 1024>>>(adj);                                           // 2
    k_mixmma<<<2048, 256, DSMMIX>>>(pXh, pXl, pYh, pYl);                    // 3
    k_mma<128, 0><<<1024, 256, DSM128>>>(pXh, pXl, pYh, pYl,                // 4 <- ncu
                                         pWLh, pWLl, nullptr, pZ,
                                         nullptr, nullptr, 8);

    // graph preprocessing
    k_init<<<256, 256>>>();
    k_hist<<<NEDGE / 256, 256>>>(sub + NEDGE);
    k_scan_partial<<<256, 256>>>();
    k_scan_block<<<1, 256>>>();
    k_scan_final<<<256, 256>>>();
    k_fill<<<NEDGE / 256, 256>>>(sub, sub + NEDGE);
    // remaining weight prep
    k_wprep<<<(512 * 128 + 255) / 256, 256>>>(gcnW + 65536, pWLh + 65536, pWLl + 65536, 512, 128);
    k_wprep<<<(512 * 128 + 255) / 256, 256>>>(gcnW + 131072, pWLh + 131072, pWLl + 131072, 512, 128);
    k_wprep<<<(128 * 128 + 255) / 256, 256>>>(W1, pW1h, pW1l, 128, 128);
    k_wprep<<<(128 * 64 + 255) / 256, 256>>>(W2, pW2h, pW2l, 128, 64);
    k_bsum<<<2, 256>>>(gcnB);

    // layer 0 aggregation (writes X pair for next layer)
    k_agg<<<NNODE / 8, 256>>>(pZ, pB, pXh, pXl);
    // layers 1..2
    for (int l = 1; l < NLAYER; l++) {
        k_mixmma<<<2048, 256, DSMMIX>>>(pXh, pXl, pYh, pYl);
        k_mma<128, 0><<<1024, 256, DSM128>>>(pXh, pXl, pYh, pYl,
                                             pWLh + (size_t)l * 65536,
                                             pWLl + (size_t)l * 65536,
                                             nullptr, pZ, nullptr, nullptr, 8);
        k_agg<<<NNODE / 8, 256>>>(pZ, pB + l * 128, pXh, pXl);
    }
    // MLP head: head1 -> Y0 pair (scratch), head2 -> out
    k_mma<128, 1><<<1024, 256, DSM128>>>(pXh, pXl, nullptr, nullptr,
                                         pW1h, pW1l, b1, nullptr, pYh, pYl, 2);
    k_mma<64, 2><<<1024, 256, DSM64>>>(pYh, pYl, nullptr, nullptr,
                                       pW2h, pW2l, b2, out, nullptr, nullptr, 2);
}